// round 11
// baseline (speedup 1.0000x reference)
#include <cuda_runtime.h>
#include <cuda_fp16.h>
#include <math.h>

#define NN 50000
#define EE 800000

// ---------------- scratch (device globals; zero-initialized at load) ----------------
__device__ float  g_sae1[EE*4];   // conv1: a_edge then OVERWRITTEN BY k_edge with exp-weights (CSR order)
__device__ float  g_sae2[EE*4];   // conv2: a_edge (CSR); overwritten by k_watt2 with exp-weights
__device__ int    g_ssrc[EE];     // src node in CSR order
__device__ int    g_sdst[EE];     // dst node in CSR order
__device__ int    g_cnt[NN];      // invariant: zero at entry (scanc re-zeroes)
__device__ int    g_cur[NN];
__device__ int    g_rowptr[NN+1];
__device__ int    g_part[128];
__device__ int    g_scancnt;      // invariant: zero at entry (last block re-zeroes)
__device__ float  g_den[NN*4];    // softmax denominators (atomic); invariant: zero at entry (k_gat re-zeroes)
__device__ float  g_h0[NN*128];
__device__ float  g_h1[NN*128];
__device__ float  g_h2[NN*128];
__device__ __half g_xsh[NN*128];  // fp16 transformed features (gather source)
__device__ float  g_asrc[NN*4];
__device__ float  g_adst[NN*4];
__device__ float  g_M[32];        // [conv*16 + j*4 + h]
__device__ float  g_CW[5*384];    // collapsed classifier: cls_w @ jk_w
__device__ float  g_cb2[5];       // collapsed bias

// ---------------- helpers ----------------
__device__ __forceinline__ unsigned long long pack2(float x){
    unsigned long long r;
    unsigned int u = __float_as_uint(x);
    asm("mov.b64 %0, {%1, %1};" : "=l"(r) : "r"(u));
    return r;
}
__device__ __forceinline__ void fma2(unsigned long long& acc,
                                     unsigned long long a, unsigned long long b){
    asm("fma.rn.f32x2 %0, %1, %2, %0;" : "+l"(acc) : "l"(a), "l"(b));
}
__device__ __forceinline__ float lo2(unsigned long long v){
    unsigned int a, b;
    asm("mov.b64 {%0, %1}, %2;" : "=r"(a), "=r"(b) : "l"(v));
    return __uint_as_float(a);
}
__device__ __forceinline__ float hi2(unsigned long long v){
    unsigned int a, b;
    asm("mov.b64 {%0, %1}, %2;" : "=r"(a), "=r"(b) : "l"(v));
    return __uint_as_float(b);
}
__device__ __forceinline__ unsigned h2u(__half2 h){
    return *reinterpret_cast<unsigned*>(&h);
}
__device__ __forceinline__ void redAdd4(float* p, float a, float b, float c, float d){
    asm volatile("red.global.add.v4.f32 [%0], {%1,%2,%3,%4};"
                 :: "l"(p), "f"(a), "f"(b), "f"(c), "f"(d) : "memory");
}

// ============ launch 1: hist + CW-prep + M-prep + node1, fused ============
#define B_HIST 782
#define B_CW   241
#define B_NODE1 1563

__global__ void __launch_bounds__(256) k_fused1(
        const int* __restrict__ ei,
        const float* __restrict__ le1, const float* __restrict__ ae1,
        const float* __restrict__ le2, const float* __restrict__ ae2,
        const float* __restrict__ cw,  const float* __restrict__ cb,
        const float* __restrict__ jkw, const float* __restrict__ jkb,
        const float* __restrict__ x,
        const float* __restrict__ pw, const float* __restrict__ pb,
        const float* __restrict__ lw,
        const float* __restrict__ asv, const float* __restrict__ adv){
    int b = blockIdx.x;
    if (b < B_HIST){
        int t = b*256 + threadIdx.x;
        if (t < EE/4){
            int4 d4 = ((const int4*)(ei+EE))[t];
            atomicAdd(&g_cnt[d4.x], 1);
            atomicAdd(&g_cnt[d4.y], 1);
            atomicAdd(&g_cnt[d4.z], 1);
            atomicAdd(&g_cnt[d4.w], 1);
        }
        return;
    }
    if (b < B_HIST + B_CW){
        int w = (b-B_HIST)*8 + (threadIdx.x >> 5);
        int lane = threadIdx.x & 31;
        if (w >= 5*385) return;
        int c = w / 385, j = w % 385;
        float4 a = *(const float4*)&cw[c*128 + lane*4];
        int d = lane*4;
        float s;
        if (j < 384){
            s = a.x*jkw[(d+0)*384+j] + a.y*jkw[(d+1)*384+j]
              + a.z*jkw[(d+2)*384+j] + a.w*jkw[(d+3)*384+j];
        } else {
            float4 bb = *(const float4*)&jkb[d];
            s = a.x*bb.x + a.y*bb.y + a.z*bb.z + a.w*bb.w;
        }
        #pragma unroll
        for (int o=16;o>0;o>>=1) s += __shfl_xor_sync(0xffffffffu, s, o);
        if (lane == 0){
            if (j < 384) g_CW[c*384+j] = s;
            else         g_cb2[c] = s + cb[c];
        }
        return;
    }
    if (b == B_HIST + B_CW){
        int t = threadIdx.x;
        if (t < 32){
            int which = t >> 4, j = (t >> 2) & 3, h = t & 3;
            const float* le = which ? le2 : le1;
            const float* ae = which ? ae2 : ae1;
            float s = 0.f;
            for (int c = 0; c < 32; c++)
                s += le[(h*32+c)*4 + j] * ae[h*32+c];
            g_M[which*16 + j*4 + h] = s;
        }
        return;
    }
    // ---- node1: two independent 128-thread halves ----
    __shared__ __align__(16) float sx[2][16*20];
    int tid = threadIdx.x;
    int sub = tid >> 7, stid = tid & 127;
    int n0 = (b - (B_HIST+B_CW+1))*32 + sub*16;
    float attS = asv[stid], attD = adv[stid], pbd = pb[stid];
    float wp[16], wl[16];
    #pragma unroll
    for (int q=0;q<4;q++){
        float4 a = *(const float4*)&pw[stid*16 + q*4];
        wp[q*4+0]=a.x; wp[q*4+1]=a.y; wp[q*4+2]=a.z; wp[q*4+3]=a.w;
        float4 bb = *(const float4*)&lw[stid*16 + q*4];
        wl[q*4+0]=bb.x; wl[q*4+1]=bb.y; wl[q*4+2]=bb.z; wl[q*4+3]=bb.w;
    }
    for (int i=stid;i<256;i+=128){
        int n=i>>4, k=i&15;
        int node=n0+n;
        sx[sub][n*20+k] = (node<NN) ? x[node*16+k] : 0.f;
    }
    __syncthreads();
    float acc0[16], acc1[16];
    #pragma unroll
    for (int n=0;n<16;n++){ acc0[n]=pbd; acc1[n]=0.f; }
    #pragma unroll
    for (int n=0;n<16;n++){
        float4 x0 = *(const float4*)&sx[sub][n*20];
        float4 x1 = *(const float4*)&sx[sub][n*20+4];
        float4 x2 = *(const float4*)&sx[sub][n*20+8];
        float4 x3 = *(const float4*)&sx[sub][n*20+12];
        float xv[16] = {x0.x,x0.y,x0.z,x0.w, x1.x,x1.y,x1.z,x1.w,
                        x2.x,x2.y,x2.z,x2.w, x3.x,x3.y,x3.z,x3.w};
        #pragma unroll
        for (int k=0;k<16;k++){
            acc0[n] = fmaf(xv[k], wp[k], acc0[n]);
            acc1[n] = fmaf(xv[k], wl[k], acc1[n]);
        }
    }
    int lane = stid&31, h = stid>>5;
    for (int n=0;n<16;n++){
        int node=n0+n;
        if (node>=NN) break;
        g_h0[node*128+stid]  = acc0[n];
        g_xsh[node*128+stid] = __float2half(acc1[n]);
        float s = acc1[n]*attS, dd = acc1[n]*attD;
        #pragma unroll
        for (int o=16;o>0;o>>=1){
            s  += __shfl_down_sync(0xffffffffu, s, o);
            dd += __shfl_down_sync(0xffffffffu, dd, o);
        }
        if (lane==0){ g_asrc[node*4+h]=s; g_adst[node*4+h]=dd; }
    }
}

// ---------------- scan: block sums + last-block scans partials ----------------
__global__ void __launch_bounds__(512) k_scanab(){
    __shared__ int sred[16];
    __shared__ int amlast;
    __shared__ int sb[128];
    int t = blockIdx.x*512 + threadIdx.x;
    int v = (t < NN) ? g_cnt[t] : 0;
    #pragma unroll
    for (int o=16;o>0;o>>=1) v += __shfl_xor_sync(0xffffffffu, v, o);
    int lane = threadIdx.x & 31, wid = threadIdx.x >> 5;
    if (lane == 0) sred[wid] = v;
    __syncthreads();
    if (threadIdx.x < 16){
        v = sred[threadIdx.x];
        #pragma unroll
        for (int o=8;o>0;o>>=1) v += __shfl_xor_sync(0xffffu, v, o);
    }
    if (threadIdx.x == 0){
        g_part[blockIdx.x] = v;
        __threadfence();
        int n = atomicAdd(&g_scancnt, 1);
        int last = (n == 97);
        if (last) g_scancnt = 0;      // restore zero-invariant
        amlast = last;
    }
    __syncthreads();
    if (amlast){
        __threadfence();
        int tt = threadIdx.x;
        int vv = 0;
        if (tt < 128){
            vv = (tt < 98) ? g_part[tt] : 0;
            sb[tt] = vv;
        }
        __syncthreads();
        for (int off=1; off<128; off<<=1){
            int u = (tt >= off && tt < 128) ? sb[tt-off] : 0;
            __syncthreads();
            if (tt < 128) sb[tt] += u;
            __syncthreads();
        }
        if (tt < 98) g_part[tt] = sb[tt] - vv;   // exclusive
    }
}

__global__ void __launch_bounds__(512) k_scanc(){
    __shared__ int s[512];
    int t = blockIdx.x*512 + threadIdx.x;
    int v = (t < NN) ? g_cnt[t] : 0;
    s[threadIdx.x] = v;
    __syncthreads();
    for (int off=1; off<512; off<<=1){
        int u = (threadIdx.x >= off) ? s[threadIdx.x-off] : 0;
        __syncthreads();
        s[threadIdx.x] += u;
        __syncthreads();
    }
    int excl = s[threadIdx.x] - v + g_part[blockIdx.x];
    if (t < NN){
        g_rowptr[t] = excl;
        g_cur[t]    = excl;
        g_cnt[t]    = 0;                // restore zero-invariant
        if (t == NN-1) g_rowptr[NN] = excl + v;
    }
}

// ---------------- edge encoder: encoder + conv1 attention weights + den + CSR scatter ----------------
#define QSTRIDE 200000   // EE/4
__global__ void __launch_bounds__(256) k_edge(
        const float* __restrict__ ea, const int* __restrict__ ei,
        const float* __restrict__ w1, const float* __restrict__ b1,
        const float* __restrict__ w2, const float* __restrict__ b2){
    __shared__ __align__(16) float sw1[256];
    __shared__ float sb1[32];
    __shared__ __align__(16) float sWM1[128];  // [c][h]
    __shared__ __align__(16) float sWM2[128];
    __shared__ float sR0[8];
    int tid = threadIdx.x;
    if (tid < 256) sw1[tid] = w1[tid];
    if (tid < 32)  sb1[tid] = b1[tid];
    if (tid < 128){
        int c = tid >> 2, h = tid & 3;
        float s1 = 0.f, s2 = 0.f;
        #pragma unroll
        for (int j=0;j<4;j++){
            float wv = w2[j*32+c];
            s1 = fmaf(wv, g_M[j*4+h],    s1);
            s2 = fmaf(wv, g_M[16+j*4+h], s2);
        }
        sWM1[c*4+h] = s1;
        sWM2[c*4+h] = s2;
    }
    if (tid >= 128 && tid < 136){
        int which = (tid-128) >> 2, h = tid & 3;
        float s = 0.f;
        #pragma unroll
        for (int j=0;j<4;j++) s = fmaf(b2[j], g_M[which*16+j*4+h], s);
        sR0[tid-128] = s;
    }
    __syncthreads();
    int gid = blockIdx.x*256 + tid;
    if (gid >= QSTRIDE) return;
    float4 A[4][2];
    #pragma unroll
    for (int q=0;q<4;q++){
        int e = gid + q*QSTRIDE;
        A[q][0] = ((const float4*)ea)[e*2];
        A[q][1] = ((const float4*)ea)[e*2+1];
    }
    float4 R10 = *(const float4*)&sR0[0];
    float4 R20 = *(const float4*)&sR0[4];
    float4 r1[4], r2[4];
    #pragma unroll
    for (int q=0;q<4;q++){ r1[q]=R10; r2[q]=R20; }
    #pragma unroll
    for (int c=0;c<32;c++){
        float4 wa = *(const float4*)&sw1[c*8];
        float4 wb = *(const float4*)&sw1[c*8+4];
        float bc  = sb1[c];
        float4 m1 = *(const float4*)&sWM1[c*4];
        float4 m2 = *(const float4*)&sWM2[c*4];
        #pragma unroll
        for (int q=0;q<4;q++){
            float hv = bc;
            hv = fmaf(wa.x, A[q][0].x, hv); hv = fmaf(wa.y, A[q][0].y, hv);
            hv = fmaf(wa.z, A[q][0].z, hv); hv = fmaf(wa.w, A[q][0].w, hv);
            hv = fmaf(wb.x, A[q][1].x, hv); hv = fmaf(wb.y, A[q][1].y, hv);
            hv = fmaf(wb.z, A[q][1].z, hv); hv = fmaf(wb.w, A[q][1].w, hv);
            hv = fmaxf(hv, 0.f);
            r1[q].x = fmaf(m1.x, hv, r1[q].x);
            r1[q].y = fmaf(m1.y, hv, r1[q].y);
            r1[q].z = fmaf(m1.z, hv, r1[q].z);
            r1[q].w = fmaf(m1.w, hv, r1[q].w);
            r2[q].x = fmaf(m2.x, hv, r2[q].x);
            r2[q].y = fmaf(m2.y, hv, r2[q].y);
            r2[q].z = fmaf(m2.z, hv, r2[q].z);
            r2[q].w = fmaf(m2.w, hv, r2[q].w);
        }
    }
    #pragma unroll
    for (int q=0;q<4;q++){
        int e = gid + q*QSTRIDE;
        int srcn = ei[e], d = ei[EE+e];
        // conv1 attention weight: exp(leaky(a_src + a_dst + a_edge))
        float4 as = ((const float4*)g_asrc)[srcn];
        float4 ad = ((const float4*)g_adst)[d];
        float ax = r1[q].x+as.x+ad.x; ax = ax>0.f?ax:0.2f*ax;
        float ay = r1[q].y+as.y+ad.y; ay = ay>0.f?ay:0.2f*ay;
        float az = r1[q].z+as.z+ad.z; az = az>0.f?az:0.2f*az;
        float aw = r1[q].w+as.w+ad.w; aw = aw>0.f?aw:0.2f*aw;
        float4 w = make_float4(__expf(ax), __expf(ay), __expf(az), __expf(aw));
        int pos = atomicAdd(&g_cur[d], 1);
        g_ssrc[pos] = srcn;
        g_sdst[pos] = d;
        ((float4*)g_sae1)[pos] = w;
        ((float4*)g_sae2)[pos] = r2[q];
        redAdd4(&g_den[d*4], w.x, w.y, w.z, w.w);
    }
}

// ---------------- conv2 attention weights (edge-parallel, after node2) ----------------
__global__ void __launch_bounds__(256) k_watt2(){
    int p = blockIdx.x*256 + threadIdx.x;
    if (p >= EE) return;
    int s = g_ssrc[p], d = g_sdst[p];
    float4 ae = ((const float4*)g_sae2)[p];
    float4 as = ((const float4*)g_asrc)[s];
    float4 ad = ((const float4*)g_adst)[d];
    float ax = ae.x+as.x+ad.x; ax = ax>0.f?ax:0.2f*ax;
    float ay = ae.y+as.y+ad.y; ay = ay>0.f?ay:0.2f*ay;
    float az = ae.z+as.z+ad.z; az = az>0.f?az:0.2f*az;
    float aw = ae.w+as.w+ad.w; aw = aw>0.f?aw:0.2f*aw;
    float4 w = make_float4(__expf(ax), __expf(ay), __expf(az), __expf(aw));
    ((float4*)g_sae2)[p] = w;
    redAdd4(&g_den[d*4], w.x, w.y, w.z, w.w);
}

// ---------------- fused GAT gather + epilogue (+ conv2: classifier/log_softmax) ----------------
__global__ void __launch_bounds__(512) k_gat(const float* __restrict__ bias,
                      const float* __restrict__ gam,
                      const float* __restrict__ bet, int conv,
                      float* __restrict__ out){
    __shared__ float2 sp[16][132];   // [warp][h*33 + j]: (src byte-offset, half2(w))
    __shared__ float sCW[1920];
    __shared__ float sCB[5];
    int tid = threadIdx.x;
    if (conv){
        for (int i=tid;i<1920;i+=512) sCW[i] = g_CW[i];
        if (tid < 5) sCB[tid] = g_cb2[tid];
    }
    __syncthreads();
    int wid = tid >> 5, lane = tid & 31;
    int node = blockIdx.x*16 + wid;
    if (node >= NN) return;
    int h = lane >> 3;
    const float4* __restrict__ warr = (const float4*)(conv ? g_sae2 : g_sae1);
    const char*   xbase = ((const char*)g_xsh) + lane*8;
    int beg = g_rowptr[node], end = g_rowptr[node+1];
    float4 dsum = ((const float4*)g_den)[node];
    if (lane == 0) ((float4*)g_den)[node] = make_float4(0.f,0.f,0.f,0.f);  // restore zero-invariant
    __half2 acc0 = __float2half2_rn(0.f);
    __half2 acc1 = __float2half2_rn(0.f);
    for (int base = beg; base < end; base += 32){
        int idx = base + lane;
        bool v = idx < end;
        int s = g_ssrc[v ? idx : end-1];
        float4 w = v ? warr[idx] : make_float4(0.f,0.f,0.f,0.f);
        float so = __uint_as_float((unsigned)s * 256u);
        __half2 u0 = __float2half2_rn(w.x);
        __half2 u1 = __float2half2_rn(w.y);
        __half2 u2 = __float2half2_rn(w.z);
        __half2 u3 = __float2half2_rn(w.w);
        __syncwarp();
        sp[wid][lane]       = make_float2(so, __uint_as_float(h2u(u0)));
        sp[wid][33 + lane]  = make_float2(so, __uint_as_float(h2u(u1)));
        sp[wid][66 + lane]  = make_float2(so, __uint_as_float(h2u(u2)));
        sp[wid][99 + lane]  = make_float2(so, __uint_as_float(h2u(u3)));
        __syncwarp();
        int cnt = end - base; if (cnt > 32) cnt = 32;
        const float2* hp2 = &sp[wid][h*33];
        for (int c = 0; c < cnt; c += 8){
            #pragma unroll
            for (int j = 0; j < 8; j++){
                float2 e2 = hp2[c+j];
                uint2 xr = *(const uint2*)(xbase + __float_as_uint(e2.x));
                unsigned wb = __float_as_uint(e2.y);
                __half2 wh = *reinterpret_cast<__half2*>(&wb);
                acc0 = __hfma2(*reinterpret_cast<__half2*>(&xr.x), wh, acc0);
                acc1 = __hfma2(*reinterpret_cast<__half2*>(&xr.y), wh, acc1);
            }
        }
    }
    float dh = (h==0)?dsum.x:(h==1)?dsum.y:(h==2)?dsum.z:dsum.w;
    float inv = 1.f/(dh + 1e-16f);
    float2 f0 = __half22float2(acc0);
    float2 f1 = __half22float2(acc1);
    const float* hp = conv ? g_h1 : g_h0;
    float*       ho = conv ? g_h2 : g_h1;
    float4 hv = ((const float4*)hp)[node*32+lane];
    float4 bv = *(const float4*)&bias[lane*4];
    float4 r;
    r.x = f0.x*inv + bv.x; r.x = (r.x>0.f)?r.x:(__expf(r.x)-1.f); r.x += hv.x;
    r.y = f0.y*inv + bv.y; r.y = (r.y>0.f)?r.y:(__expf(r.y)-1.f); r.y += hv.y;
    r.z = f1.x*inv + bv.z; r.z = (r.z>0.f)?r.z:(__expf(r.z)-1.f); r.z += hv.z;
    r.w = f1.y*inv + bv.w; r.w = (r.w>0.f)?r.w:(__expf(r.w)-1.f); r.w += hv.w;
    float s1 = r.x+r.y+r.z+r.w;
    float s2 = r.x*r.x + r.y*r.y + r.z*r.z + r.w*r.w;
    #pragma unroll
    for (int o=16;o>0;o>>=1){
        s1 += __shfl_xor_sync(0xffffffffu, s1, o);
        s2 += __shfl_xor_sync(0xffffffffu, s2, o);
    }
    float mu  = s1 * (1.f/128.f);
    float var = s2 * (1.f/128.f) - mu*mu;
    float rs  = rsqrtf(var + 1e-5f);
    float4 gv = *(const float4*)&gam[lane*4];
    float4 be = *(const float4*)&bet[lane*4];
    float4 o4;
    o4.x = (r.x-mu)*rs*gv.x + be.x;
    o4.y = (r.y-mu)*rs*gv.y + be.y;
    o4.z = (r.z-mu)*rs*gv.z + be.z;
    o4.w = (r.w-mu)*rs*gv.w + be.w;
    ((float4*)ho)[node*32+lane] = o4;

    if (conv){
        float4 a0 = ((const float4*)g_h0)[node*32+lane];
        float lg[5];
        #pragma unroll
        for (int c=0;c<5;c++){
            const float* w = &sCW[c*384];
            float4 b0 = *(const float4*)&w[lane*4];
            float4 b1 = *(const float4*)&w[128 + lane*4];
            float4 b2 = *(const float4*)&w[256 + lane*4];
            float p = a0.x*b0.x + a0.y*b0.y + a0.z*b0.z + a0.w*b0.w;
            p = fmaf(hv.x,b1.x, fmaf(hv.y,b1.y, fmaf(hv.z,b1.z, fmaf(hv.w,b1.w, p))));
            p = fmaf(o4.x,b2.x, fmaf(o4.y,b2.y, fmaf(o4.z,b2.z, fmaf(o4.w,b2.w, p))));
            #pragma unroll
            for (int o=16;o>0;o>>=1) p += __shfl_xor_sync(0xffffffffu, p, o);
            lg[c] = p + sCB[c];
        }
        if (lane == 0){
            float m = lg[0];
            #pragma unroll
            for (int c=1;c<5;c++) m = fmaxf(m, lg[c]);
            float s = 0.f;
            #pragma unroll
            for (int c=0;c<5;c++) s += __expf(lg[c]-m);
            float ls = logf(s);
            #pragma unroll
            for (int c=0;c<5;c++) out[node*5+c] = lg[c]-m-ls;
        }
    }
}

// ---------------- conv2 GEMM + fused attention dots (fp16 xs output) ----------------
__global__ void __launch_bounds__(256) k_node2(const float* __restrict__ lin,
                                               const float* __restrict__ asv,
                                               const float* __restrict__ adv){
    __shared__ float sA[16*132];
    __shared__ float sB[16*132];
    int tid = threadIdx.x;
    int tx = tid & 15, ty = tid >> 4;
    int n0 = blockIdx.x*128;
    unsigned long long acc[8][4];
    #pragma unroll
    for (int r=0;r<8;r++)
        #pragma unroll
        for (int p=0;p<4;p++) acc[r][p] = 0ULL;
    for (int kc=0;kc<8;kc++){
        __syncthreads();
        #pragma unroll
        for (int t=tid;t<512;t+=256){
            int r = t>>2, q = t&3;
            int node = n0 + r;
            float4 v = (node<NN) ? *(const float4*)&g_h1[node*128 + kc*16 + q*4]
                                 : make_float4(0.f,0.f,0.f,0.f);
            sA[(q*4+0)*132+r]=v.x; sA[(q*4+1)*132+r]=v.y;
            sA[(q*4+2)*132+r]=v.z; sA[(q*4+3)*132+r]=v.w;
        }
        #pragma unroll
        for (int t=tid;t<512;t+=256){
            int d = t>>2, q = t&3;
            float4 v = *(const float4*)&lin[d*128 + kc*16 + q*4];
            sB[(q*4+0)*132+d]=v.x; sB[(q*4+1)*132+d]=v.y;
            sB[(q*4+2)*132+d]=v.z; sB[(q*4+3)*132+d]=v.w;
        }
        __syncthreads();
        #pragma unroll
        for (int k=0;k<16;k++){
            float4 a0 = *(const float4*)&sA[k*132 + ty*8];
            float4 a1 = *(const float4*)&sA[k*132 + ty*8 + 4];
            ulonglong2 b0 = *(const ulonglong2*)&sB[k*132 + tx*8];
            ulonglong2 b1 = *(const ulonglong2*)&sB[k*132 + tx*8 + 4];
            unsigned long long bp0=b0.x, bp1=b0.y, bp2=b1.x, bp3=b1.y;
            float ar[8] = {a0.x,a0.y,a0.z,a0.w,a1.x,a1.y,a1.z,a1.w};
            #pragma unroll
            for (int r=0;r<8;r++){
                unsigned long long a2 = pack2(ar[r]);
                fma2(acc[r][0], a2, bp0);
                fma2(acc[r][1], a2, bp1);
                fma2(acc[r][2], a2, bp2);
                fma2(acc[r][3], a2, bp3);
            }
        }
    }
    float4 ws0 = *(const float4*)&asv[tx*8];
    float4 ws1 = *(const float4*)&asv[tx*8+4];
    float4 wd0 = *(const float4*)&adv[tx*8];
    float4 wd1 = *(const float4*)&adv[tx*8+4];
    int hh = tx >> 2;
    #pragma unroll
    for (int r=0;r<8;r++){
        int node = n0 + ty*8 + r;
        if (node < NN){
            float f0=lo2(acc[r][0]), f1=hi2(acc[r][0]);
            float f2=lo2(acc[r][1]), f3=hi2(acc[r][1]);
            float f4=lo2(acc[r][2]), f5=hi2(acc[r][2]);
            float f6=lo2(acc[r][3]), f7=hi2(acc[r][3]);
            uint4 st;
            st.x = h2u(__floats2half2_rn(f0, f1));
            st.y = h2u(__floats2half2_rn(f2, f3));
            st.z = h2u(__floats2half2_rn(f4, f5));
            st.w = h2u(__floats2half2_rn(f6, f7));
            *(uint4*)(((char*)g_xsh) + node*256 + tx*16) = st;
            float s = f0*ws0.x + f1*ws0.y + f2*ws0.z + f3*ws0.w
                    + f4*ws1.x + f5*ws1.y + f6*ws1.z + f7*ws1.w;
            float d = f0*wd0.x + f1*wd0.y + f2*wd0.z + f3*wd0.w
                    + f4*wd1.x + f5*wd1.y + f6*wd1.z + f7*wd1.w;
            s += __shfl_xor_sync(0xffffffffu, s, 1);
            s += __shfl_xor_sync(0xffffffffu, s, 2);
            d += __shfl_xor_sync(0xffffffffu, d, 1);
            d += __shfl_xor_sync(0xffffffffu, d, 2);
            if ((tx & 3) == 0){
                g_asrc[node*4+hh] = s;
                g_adst[node*4+hh] = d;
            }
        }
    }
}

// ---------------- launcher ----------------
extern "C" void kernel_launch(void* const* d_in, const int* in_sizes, int n_in,
                              void* d_out, int out_size){
    const float* x      = (const float*)d_in[0];
    const int*   ei     = (const int*)  d_in[1];
    const float* ea     = (const float*)d_in[2];
    const float* ee_w1  = (const float*)d_in[3];
    const float* ee_b1  = (const float*)d_in[4];
    const float* ee_w2  = (const float*)d_in[5];
    const float* ee_b2  = (const float*)d_in[6];
    const float* proj_w = (const float*)d_in[7];
    const float* proj_b = (const float*)d_in[8];
    const float* c1_lin = (const float*)d_in[9];
    const float* c1_as  = (const float*)d_in[10];
    const float* c1_ad  = (const float*)d_in[11];
    const float* c1_le  = (const float*)d_in[12];
    const float* c1_ae  = (const float*)d_in[13];
    const float* c1_b   = (const float*)d_in[14];
    const float* c2_lin = (const float*)d_in[15];
    const float* c2_as  = (const float*)d_in[16];
    const float* c2_ad  = (const float*)d_in[17];
    const float* c2_le  = (const float*)d_in[18];
    const float* c2_ae  = (const float*)d_in[19];
    const float* c2_b   = (const float*)d_in[20];
    const float* n1_g   = (const float*)d_in[21];
    const float* n1_b   = (const float*)d_in[22];
    const float* n2_g   = (const float*)d_in[23];
    const float* n2_b   = (const float*)d_in[24];
    const float* jk_w   = (const float*)d_in[25];
    const float* jk_b   = (const float*)d_in[26];
    const float* cls_w  = (const float*)d_in[27];
    const float* cls_b  = (const float*)d_in[28];
    float* out = (float*)d_out;

    k_fused1<<<B_HIST+B_CW+1+B_NODE1,256>>>(ei, c1_le, c1_ae, c2_le, c2_ae,
                                            cls_w, cls_b, jk_w, jk_b,
                                            x, proj_w, proj_b, c1_lin, c1_as, c1_ad);
    k_scanab<<<98,512>>>();
    k_scanc<<<98,512>>>();
    k_edge<<<(QSTRIDE+255)/256,256>>>(ea, ei, ee_w1, ee_b1, ee_w2, ee_b2);   // profiled slot
    k_gat<<<(NN+15)/16,512>>>(c1_b, n1_g, n1_b, 0, out);
    k_node2<<<(NN+127)/128,256>>>(c2_lin, c2_as, c2_ad);
    k_watt2<<<(EE+255)/256,256>>>();
    k_gat<<<(NN+15)/16,512>>>(c2_b, n2_g, n2_b, 1, out);
}

// round 12
// speedup vs baseline: 1.1979x; 1.1979x over previous
#include <cuda_runtime.h>
#include <cuda_fp16.h>
#include <math.h>

#define NN 50000
#define EE 800000

// ---------------- scratch (device globals; zero-initialized at load) ----------------
__device__ float  g_sae1[EE*4];   // a_edge (conv1) in CSR order
__device__ float  g_sae2[EE*4];   // a_edge (conv2) in CSR order
__device__ int    g_ssrc[EE];     // src node in CSR order
__device__ int    g_cnt[NN];      // invariant: zero at entry (scanc re-zeroes)
__device__ int    g_cur[NN];
__device__ int    g_rowptr[NN+1];
__device__ int    g_part[128];
__device__ int    g_scancnt;      // invariant: zero at entry (last block re-zeroes)
__device__ float  g_h0[NN*128];
__device__ float  g_h1[NN*128];
__device__ float  g_h2[NN*128];
__device__ __half g_xsh[NN*128];  // fp16 transformed features (gather source)
__device__ float  g_asrc[NN*4];
__device__ float  g_adst[NN*4];
__device__ float  g_M[32];        // [conv*16 + j*4 + h]
__device__ float  g_CW[5*384];    // collapsed classifier: cls_w @ jk_w
__device__ float  g_cb2[5];       // collapsed bias

// ---------------- helpers ----------------
__device__ __forceinline__ unsigned long long pack2(float x){
    unsigned long long r;
    unsigned int u = __float_as_uint(x);
    asm("mov.b64 %0, {%1, %1};" : "=l"(r) : "r"(u));
    return r;
}
__device__ __forceinline__ void fma2(unsigned long long& acc,
                                     unsigned long long a, unsigned long long b){
    asm("fma.rn.f32x2 %0, %1, %2, %0;" : "+l"(acc) : "l"(a), "l"(b));
}
__device__ __forceinline__ float lo2(unsigned long long v){
    unsigned int a, b;
    asm("mov.b64 {%0, %1}, %2;" : "=r"(a), "=r"(b) : "l"(v));
    return __uint_as_float(a);
}
__device__ __forceinline__ float hi2(unsigned long long v){
    unsigned int a, b;
    asm("mov.b64 {%0, %1}, %2;" : "=r"(a), "=r"(b) : "l"(v));
    return __uint_as_float(b);
}
__device__ __forceinline__ unsigned h2u(__half2 h){
    return *reinterpret_cast<unsigned*>(&h);
}

// ============ launch 1: hist + CW-prep + M-prep + node1, fused ============
#define B_HIST 782
#define B_CW   241
#define B_NODE1 1563

__global__ void __launch_bounds__(256) k_fused1(
        const int* __restrict__ ei,
        const float* __restrict__ le1, const float* __restrict__ ae1,
        const float* __restrict__ le2, const float* __restrict__ ae2,
        const float* __restrict__ cw,  const float* __restrict__ cb,
        const float* __restrict__ jkw, const float* __restrict__ jkb,
        const float* __restrict__ x,
        const float* __restrict__ pw, const float* __restrict__ pb,
        const float* __restrict__ lw,
        const float* __restrict__ asv, const float* __restrict__ adv){
    int b = blockIdx.x;
    if (b < B_HIST){
        int t = b*256 + threadIdx.x;
        if (t < EE/4){
            int4 d4 = ((const int4*)(ei+EE))[t];
            atomicAdd(&g_cnt[d4.x], 1);
            atomicAdd(&g_cnt[d4.y], 1);
            atomicAdd(&g_cnt[d4.z], 1);
            atomicAdd(&g_cnt[d4.w], 1);
        }
        return;
    }
    if (b < B_HIST + B_CW){
        int w = (b-B_HIST)*8 + (threadIdx.x >> 5);
        int lane = threadIdx.x & 31;
        if (w >= 5*385) return;
        int c = w / 385, j = w % 385;
        float4 a = *(const float4*)&cw[c*128 + lane*4];
        int d = lane*4;
        float s;
        if (j < 384){
            s = a.x*jkw[(d+0)*384+j] + a.y*jkw[(d+1)*384+j]
              + a.z*jkw[(d+2)*384+j] + a.w*jkw[(d+3)*384+j];
        } else {
            float4 bb = *(const float4*)&jkb[d];
            s = a.x*bb.x + a.y*bb.y + a.z*bb.z + a.w*bb.w;
        }
        #pragma unroll
        for (int o=16;o>0;o>>=1) s += __shfl_xor_sync(0xffffffffu, s, o);
        if (lane == 0){
            if (j < 384) g_CW[c*384+j] = s;
            else         g_cb2[c] = s + cb[c];
        }
        return;
    }
    if (b == B_HIST + B_CW){
        int t = threadIdx.x;
        if (t < 32){
            int which = t >> 4, j = (t >> 2) & 3, h = t & 3;
            const float* le = which ? le2 : le1;
            const float* ae = which ? ae2 : ae1;
            float s = 0.f;
            for (int c = 0; c < 32; c++)
                s += le[(h*32+c)*4 + j] * ae[h*32+c];
            g_M[which*16 + j*4 + h] = s;
        }
        return;
    }
    // ---- node1: two independent 128-thread halves ----
    __shared__ __align__(16) float sx[2][16*20];
    int tid = threadIdx.x;
    int sub = tid >> 7, stid = tid & 127;
    int n0 = (b - (B_HIST+B_CW+1))*32 + sub*16;
    float attS = asv[stid], attD = adv[stid], pbd = pb[stid];
    float wp[16], wl[16];
    #pragma unroll
    for (int q=0;q<4;q++){
        float4 a = *(const float4*)&pw[stid*16 + q*4];
        wp[q*4+0]=a.x; wp[q*4+1]=a.y; wp[q*4+2]=a.z; wp[q*4+3]=a.w;
        float4 bb = *(const float4*)&lw[stid*16 + q*4];
        wl[q*4+0]=bb.x; wl[q*4+1]=bb.y; wl[q*4+2]=bb.z; wl[q*4+3]=bb.w;
    }
    for (int i=stid;i<256;i+=128){
        int n=i>>4, k=i&15;
        int node=n0+n;
        sx[sub][n*20+k] = (node<NN) ? x[node*16+k] : 0.f;
    }
    __syncthreads();
    float acc0[16], acc1[16];
    #pragma unroll
    for (int n=0;n<16;n++){ acc0[n]=pbd; acc1[n]=0.f; }
    #pragma unroll
    for (int n=0;n<16;n++){
        float4 x0 = *(const float4*)&sx[sub][n*20];
        float4 x1 = *(const float4*)&sx[sub][n*20+4];
        float4 x2 = *(const float4*)&sx[sub][n*20+8];
        float4 x3 = *(const float4*)&sx[sub][n*20+12];
        float xv[16] = {x0.x,x0.y,x0.z,x0.w, x1.x,x1.y,x1.z,x1.w,
                        x2.x,x2.y,x2.z,x2.w, x3.x,x3.y,x3.z,x3.w};
        #pragma unroll
        for (int k=0;k<16;k++){
            acc0[n] = fmaf(xv[k], wp[k], acc0[n]);
            acc1[n] = fmaf(xv[k], wl[k], acc1[n]);
        }
    }
    int lane = stid&31, h = stid>>5;
    for (int n=0;n<16;n++){
        int node=n0+n;
        if (node>=NN) break;
        g_h0[node*128+stid]  = acc0[n];
        g_xsh[node*128+stid] = __float2half(acc1[n]);
        float s = acc1[n]*attS, dd = acc1[n]*attD;
        #pragma unroll
        for (int o=16;o>0;o>>=1){
            s  += __shfl_down_sync(0xffffffffu, s, o);
            dd += __shfl_down_sync(0xffffffffu, dd, o);
        }
        if (lane==0){ g_asrc[node*4+h]=s; g_adst[node*4+h]=dd; }
    }
}

// ---------------- scan: block sums + last-block scans partials ----------------
__global__ void __launch_bounds__(512) k_scanab(){
    __shared__ int sred[16];
    __shared__ int amlast;
    __shared__ int sb[128];
    int t = blockIdx.x*512 + threadIdx.x;
    int v = (t < NN) ? g_cnt[t] : 0;
    #pragma unroll
    for (int o=16;o>0;o>>=1) v += __shfl_xor_sync(0xffffffffu, v, o);
    int lane = threadIdx.x & 31, wid = threadIdx.x >> 5;
    if (lane == 0) sred[wid] = v;
    __syncthreads();
    if (threadIdx.x < 16){
        v = sred[threadIdx.x];
        #pragma unroll
        for (int o=8;o>0;o>>=1) v += __shfl_xor_sync(0xffffu, v, o);
    }
    if (threadIdx.x == 0){
        g_part[blockIdx.x] = v;
        __threadfence();
        int n = atomicAdd(&g_scancnt, 1);
        int last = (n == 97);
        if (last) g_scancnt = 0;      // restore zero-invariant
        amlast = last;
    }
    __syncthreads();
    if (amlast){
        __threadfence();
        int tt = threadIdx.x;
        int vv = 0;
        if (tt < 128){
            vv = (tt < 98) ? g_part[tt] : 0;
            sb[tt] = vv;
        }
        __syncthreads();
        for (int off=1; off<128; off<<=1){
            int u = (tt >= off && tt < 128) ? sb[tt-off] : 0;
            __syncthreads();
            if (tt < 128) sb[tt] += u;
            __syncthreads();
        }
        if (tt < 98) g_part[tt] = sb[tt] - vv;   // exclusive
    }
}

__global__ void __launch_bounds__(512) k_scanc(){
    __shared__ int s[512];
    int t = blockIdx.x*512 + threadIdx.x;
    int v = (t < NN) ? g_cnt[t] : 0;
    s[threadIdx.x] = v;
    __syncthreads();
    for (int off=1; off<512; off<<=1){
        int u = (threadIdx.x >= off) ? s[threadIdx.x-off] : 0;
        __syncthreads();
        s[threadIdx.x] += u;
        __syncthreads();
    }
    int excl = s[threadIdx.x] - v + g_part[blockIdx.x];
    if (t < NN){
        g_rowptr[t] = excl;
        g_cur[t]    = excl;
        g_cnt[t]    = 0;                // restore zero-invariant
        if (t == NN-1) g_rowptr[NN] = excl + v;
    }
}

// ---------------- edge encoder: 4 edges/thread, WM-folded, coalesced (R9/R10-proven) ----------------
#define QSTRIDE 200000   // EE/4
__global__ void __launch_bounds__(256) k_edge(
        const float* __restrict__ ea, const int* __restrict__ ei,
        const float* __restrict__ w1, const float* __restrict__ b1,
        const float* __restrict__ w2, const float* __restrict__ b2){
    __shared__ __align__(16) float sw1[256];
    __shared__ float sb1[32];
    __shared__ __align__(16) float sWM1[128];  // [c][h]
    __shared__ __align__(16) float sWM2[128];
    __shared__ float sR0[8];
    int tid = threadIdx.x;
    if (tid < 256) sw1[tid] = w1[tid];
    if (tid < 32)  sb1[tid] = b1[tid];
    if (tid < 128){
        int c = tid >> 2, h = tid & 3;
        float s1 = 0.f, s2 = 0.f;
        #pragma unroll
        for (int j=0;j<4;j++){
            float wv = w2[j*32+c];
            s1 = fmaf(wv, g_M[j*4+h],    s1);
            s2 = fmaf(wv, g_M[16+j*4+h], s2);
        }
        sWM1[c*4+h] = s1;
        sWM2[c*4+h] = s2;
    }
    if (tid >= 128 && tid < 136){
        int which = (tid-128) >> 2, h = tid & 3;
        float s = 0.f;
        #pragma unroll
        for (int j=0;j<4;j++) s = fmaf(b2[j], g_M[which*16+j*4+h], s);
        sR0[tid-128] = s;
    }
    __syncthreads();
    int gid = blockIdx.x*256 + tid;
    if (gid >= QSTRIDE) return;
    float4 A[4][2];
    #pragma unroll
    for (int q=0;q<4;q++){
        int e = gid + q*QSTRIDE;
        A[q][0] = ((const float4*)ea)[e*2];
        A[q][1] = ((const float4*)ea)[e*2+1];
    }
    float4 R10 = *(const float4*)&sR0[0];
    float4 R20 = *(const float4*)&sR0[4];
    float4 r1[4], r2[4];
    #pragma unroll
    for (int q=0;q<4;q++){ r1[q]=R10; r2[q]=R20; }
    #pragma unroll
    for (int c=0;c<32;c++){
        float4 wa = *(const float4*)&sw1[c*8];
        float4 wb = *(const float4*)&sw1[c*8+4];
        float bc  = sb1[c];
        float4 m1 = *(const float4*)&sWM1[c*4];
        float4 m2 = *(const float4*)&sWM2[c*4];
        #pragma unroll
        for (int q=0;q<4;q++){
            float hv = bc;
            hv = fmaf(wa.x, A[q][0].x, hv); hv = fmaf(wa.y, A[q][0].y, hv);
            hv = fmaf(wa.z, A[q][0].z, hv); hv = fmaf(wa.w, A[q][0].w, hv);
            hv = fmaf(wb.x, A[q][1].x, hv); hv = fmaf(wb.y, A[q][1].y, hv);
            hv = fmaf(wb.z, A[q][1].z, hv); hv = fmaf(wb.w, A[q][1].w, hv);
            hv = fmaxf(hv, 0.f);
            r1[q].x = fmaf(m1.x, hv, r1[q].x);
            r1[q].y = fmaf(m1.y, hv, r1[q].y);
            r1[q].z = fmaf(m1.z, hv, r1[q].z);
            r1[q].w = fmaf(m1.w, hv, r1[q].w);
            r2[q].x = fmaf(m2.x, hv, r2[q].x);
            r2[q].y = fmaf(m2.y, hv, r2[q].y);
            r2[q].z = fmaf(m2.z, hv, r2[q].z);
            r2[q].w = fmaf(m2.w, hv, r2[q].w);
        }
    }
    #pragma unroll
    for (int q=0;q<4;q++){
        int e = gid + q*QSTRIDE;
        int srcn = ei[e], d = ei[EE+e];
        int pos = atomicAdd(&g_cur[d], 1);
        g_ssrc[pos] = srcn;
        ((float4*)g_sae1)[pos] = r1[q];
        ((float4*)g_sae2)[pos] = r2[q];
    }
}

// ---------------- fused GAT conv (HFMA2 gather) + (conv2) classifier/log_softmax ----------------
__global__ void __launch_bounds__(512) k_gat(const float* __restrict__ bias,
                      const float* __restrict__ gam,
                      const float* __restrict__ bet, int conv,
                      float* __restrict__ out){
    __shared__ float2 sp[16][132];   // [warp][h*33 + j]: (src byte-offset, half2(w))
    __shared__ float sCW[1920];
    __shared__ float sCB[5];
    int tid = threadIdx.x;
    if (conv){
        for (int i=tid;i<1920;i+=512) sCW[i] = g_CW[i];
        if (tid < 5) sCB[tid] = g_cb2[tid];
    }
    __syncthreads();
    int wid = tid >> 5, lane = tid & 31;
    int node = blockIdx.x*16 + wid;
    if (node >= NN) return;
    int h = lane >> 3;
    const float4* __restrict__ sae   = (const float4*)(conv ? g_sae2 : g_sae1);
    const float4* __restrict__ asrc4 = (const float4*)g_asrc;
    const char*   xbase = ((const char*)g_xsh) + lane*8;
    float4 ad = ((const float4*)g_adst)[node];
    int beg = g_rowptr[node], end = g_rowptr[node+1];
    float4 den = make_float4(0.f,0.f,0.f,0.f);
    __half2 acc0 = __float2half2_rn(0.f);
    __half2 acc1 = __float2half2_rn(0.f);
    for (int base = beg; base < end; base += 32){
        int idx = base + lane;
        bool v = idx < end;
        int s = g_ssrc[v ? idx : end-1];
        float4 w = make_float4(0.f,0.f,0.f,0.f);
        if (v){
            float4 ae = sae[idx];
            float4 as = asrc4[s];
            float ax = as.x+ad.x+ae.x; ax = ax>0.f?ax:0.2f*ax;
            float ay = as.y+ad.y+ae.y; ay = ay>0.f?ay:0.2f*ay;
            float az = as.z+ad.z+ae.z; az = az>0.f?az:0.2f*az;
            float aw = as.w+ad.w+ae.w; aw = aw>0.f?aw:0.2f*aw;
            w = make_float4(__expf(ax), __expf(ay), __expf(az), __expf(aw));
        }
        den.x += w.x; den.y += w.y; den.z += w.z; den.w += w.w;
        float so = __uint_as_float((unsigned)s * 256u);   // byte offset of fp16 row
        __syncwarp();
        sp[wid][lane]       = make_float2(so, __uint_as_float(h2u(__float2half2_rn(w.x))));
        sp[wid][33 + lane]  = make_float2(so, __uint_as_float(h2u(__float2half2_rn(w.y))));
        sp[wid][66 + lane]  = make_float2(so, __uint_as_float(h2u(__float2half2_rn(w.z))));
        sp[wid][99 + lane]  = make_float2(so, __uint_as_float(h2u(__float2half2_rn(w.w))));
        __syncwarp();
        int cnt = end - base; if (cnt > 32) cnt = 32;
        const float2* hp2 = &sp[wid][h*33];
        for (int c = 0; c < cnt; c += 8){
            #pragma unroll
            for (int j = 0; j < 8; j++){
                float2 e2 = hp2[c+j];
                uint2 xr = *(const uint2*)(xbase + __float_as_uint(e2.x));
                unsigned wb = __float_as_uint(e2.y);
                __half2 wh = *reinterpret_cast<__half2*>(&wb);
                acc0 = __hfma2(*reinterpret_cast<__half2*>(&xr.x), wh, acc0);
                acc1 = __hfma2(*reinterpret_cast<__half2*>(&xr.y), wh, acc1);
            }
        }
    }
    #pragma unroll
    for (int o=16;o>0;o>>=1){
        den.x += __shfl_xor_sync(0xffffffffu, den.x, o);
        den.y += __shfl_xor_sync(0xffffffffu, den.y, o);
        den.z += __shfl_xor_sync(0xffffffffu, den.z, o);
        den.w += __shfl_xor_sync(0xffffffffu, den.w, o);
    }
    float dh = (h==0)?den.x:(h==1)?den.y:(h==2)?den.z:den.w;
    float inv = 1.f/(dh + 1e-16f);
    float2 f0 = __half22float2(acc0);
    float2 f1 = __half22float2(acc1);
    const float* hp = conv ? g_h1 : g_h0;
    float*       ho = conv ? g_h2 : g_h1;
    float4 hv = ((const float4*)hp)[node*32+lane];
    float4 bv = *(const float4*)&bias[lane*4];
    float4 r;
    r.x = f0.x*inv + bv.x; r.x = (r.x>0.f)?r.x:(__expf(r.x)-1.f); r.x += hv.x;
    r.y = f0.y*inv + bv.y; r.y = (r.y>0.f)?r.y:(__expf(r.y)-1.f); r.y += hv.y;
    r.z = f1.x*inv + bv.z; r.z = (r.z>0.f)?r.z:(__expf(r.z)-1.f); r.z += hv.z;
    r.w = f1.y*inv + bv.w; r.w = (r.w>0.f)?r.w:(__expf(r.w)-1.f); r.w += hv.w;
    float s1 = r.x+r.y+r.z+r.w;
    float s2 = r.x*r.x + r.y*r.y + r.z*r.z + r.w*r.w;
    #pragma unroll
    for (int o=16;o>0;o>>=1){
        s1 += __shfl_xor_sync(0xffffffffu, s1, o);
        s2 += __shfl_xor_sync(0xffffffffu, s2, o);
    }
    float mu  = s1 * (1.f/128.f);
    float var = s2 * (1.f/128.f) - mu*mu;
    float rs  = rsqrtf(var + 1e-5f);
    float4 gv = *(const float4*)&gam[lane*4];
    float4 be = *(const float4*)&bet[lane*4];
    float4 o4;
    o4.x = (r.x-mu)*rs*gv.x + be.x;
    o4.y = (r.y-mu)*rs*gv.y + be.y;
    o4.z = (r.z-mu)*rs*gv.z + be.z;
    o4.w = (r.w-mu)*rs*gv.w + be.w;
    ((float4*)ho)[node*32+lane] = o4;

    if (conv){
        float4 a0 = ((const float4*)g_h0)[node*32+lane];
        float lg[5];
        #pragma unroll
        for (int c=0;c<5;c++){
            const float* w = &sCW[c*384];
            float4 b0 = *(const float4*)&w[lane*4];
            float4 b1 = *(const float4*)&w[128 + lane*4];
            float4 b2 = *(const float4*)&w[256 + lane*4];
            float p = a0.x*b0.x + a0.y*b0.y + a0.z*b0.z + a0.w*b0.w;
            p = fmaf(hv.x,b1.x, fmaf(hv.y,b1.y, fmaf(hv.z,b1.z, fmaf(hv.w,b1.w, p))));
            p = fmaf(o4.x,b2.x, fmaf(o4.y,b2.y, fmaf(o4.z,b2.z, fmaf(o4.w,b2.w, p))));
            #pragma unroll
            for (int o=16;o>0;o>>=1) p += __shfl_xor_sync(0xffffffffu, p, o);
            lg[c] = p + sCB[c];
        }
        if (lane == 0){
            float m = lg[0];
            #pragma unroll
            for (int c=1;c<5;c++) m = fmaxf(m, lg[c]);
            float s = 0.f;
            #pragma unroll
            for (int c=0;c<5;c++) s += __expf(lg[c]-m);
            float ls = logf(s);
            #pragma unroll
            for (int c=0;c<5;c++) out[node*5+c] = lg[c]-m-ls;
        }
    }
}

// ---------------- conv2 GEMM + fused attention dots (fp16 xs output) ----------------
__global__ void __launch_bounds__(256) k_node2(const float* __restrict__ lin,
                                               const float* __restrict__ asv,
                                               const float* __restrict__ adv){
    __shared__ float sA[16*132];
    __shared__ float sB[16*132];
    int tid = threadIdx.x;
    int tx = tid & 15, ty = tid >> 4;
    int n0 = blockIdx.x*128;
    unsigned long long acc[8][4];
    #pragma unroll
    for (int r=0;r<8;r++)
        #pragma unroll
        for (int p=0;p<4;p++) acc[r][p] = 0ULL;
    for (int kc=0;kc<8;kc++){
        __syncthreads();
        #pragma unroll
        for (int t=tid;t<512;t+=256){
            int r = t>>2, q = t&3;
            int node = n0 + r;
            float4 v = (node<NN) ? *(const float4*)&g_h1[node*128 + kc*16 + q*4]
                                 : make_float4(0.f,0.f,0.f,0.f);
            sA[(q*4+0)*132+r]=v.x; sA[(q*4+1)*132+r]=v.y;
            sA[(q*4+2)*132+r]=v.z; sA[(q*4+3)*132+r]=v.w;
        }
        #pragma unroll
        for (int t=tid;t<512;t+=256){
            int d = t>>2, q = t&3;
            float4 v = *(const float4*)&lin[d*128 + kc*16 + q*4];
            sB[(q*4+0)*132+d]=v.x; sB[(q*4+1)*132+d]=v.y;
            sB[(q*4+2)*132+d]=v.z; sB[(q*4+3)*132+d]=v.w;
        }
        __syncthreads();
        #pragma unroll
        for (int k=0;k<16;k++){
            float4 a0 = *(const float4*)&sA[k*132 + ty*8];
            float4 a1 = *(const float4*)&sA[k*132 + ty*8 + 4];
            ulonglong2 b0 = *(const ulonglong2*)&sB[k*132 + tx*8];
            ulonglong2 b1 = *(const ulonglong2*)&sB[k*132 + tx*8 + 4];
            unsigned long long bp0=b0.x, bp1=b0.y, bp2=b1.x, bp3=b1.y;
            float ar[8] = {a0.x,a0.y,a0.z,a0.w,a1.x,a1.y,a1.z,a1.w};
            #pragma unroll
            for (int r=0;r<8;r++){
                unsigned long long a2 = pack2(ar[r]);
                fma2(acc[r][0], a2, bp0);
                fma2(acc[r][1], a2, bp1);
                fma2(acc[r][2], a2, bp2);
                fma2(acc[r][3], a2, bp3);
            }
        }
    }
    float4 ws0 = *(const float4*)&asv[tx*8];
    float4 ws1 = *(const float4*)&asv[tx*8+4];
    float4 wd0 = *(const float4*)&adv[tx*8];
    float4 wd1 = *(const float4*)&adv[tx*8+4];
    int hh = tx >> 2;
    #pragma unroll
    for (int r=0;r<8;r++){
        int node = n0 + ty*8 + r;
        if (node < NN){
            float f0=lo2(acc[r][0]), f1=hi2(acc[r][0]);
            float f2=lo2(acc[r][1]), f3=hi2(acc[r][1]);
            float f4=lo2(acc[r][2]), f5=hi2(acc[r][2]);
            float f6=lo2(acc[r][3]), f7=hi2(acc[r][3]);
            uint4 st;
            st.x = h2u(__floats2half2_rn(f0, f1));
            st.y = h2u(__floats2half2_rn(f2, f3));
            st.z = h2u(__floats2half2_rn(f4, f5));
            st.w = h2u(__floats2half2_rn(f6, f7));
            *(uint4*)(((char*)g_xsh) + node*256 + tx*16) = st;
            float s = f0*ws0.x + f1*ws0.y + f2*ws0.z + f3*ws0.w
                    + f4*ws1.x + f5*ws1.y + f6*ws1.z + f7*ws1.w;
            float d = f0*wd0.x + f1*wd0.y + f2*wd0.z + f3*wd0.w
                    + f4*wd1.x + f5*wd1.y + f6*wd1.z + f7*wd1.w;
            s += __shfl_xor_sync(0xffffffffu, s, 1);
            s += __shfl_xor_sync(0xffffffffu, s, 2);
            d += __shfl_xor_sync(0xffffffffu, d, 1);
            d += __shfl_xor_sync(0xffffffffu, d, 2);
            if ((tx & 3) == 0){
                g_asrc[node*4+hh] = s;
                g_adst[node*4+hh] = d;
            }
        }
    }
}

// ---------------- launcher ----------------
extern "C" void kernel_launch(void* const* d_in, const int* in_sizes, int n_in,
                              void* d_out, int out_size){
    const float* x      = (const float*)d_in[0];
    const int*   ei     = (const int*)  d_in[1];
    const float* ea     = (const float*)d_in[2];
    const float* ee_w1  = (const float*)d_in[3];
    const float* ee_b1  = (const float*)d_in[4];
    const float* ee_w2  = (const float*)d_in[5];
    const float* ee_b2  = (const float*)d_in[6];
    const float* proj_w = (const float*)d_in[7];
    const float* proj_b = (const float*)d_in[8];
    const float* c1_lin = (const float*)d_in[9];
    const float* c1_as  = (const float*)d_in[10];
    const float* c1_ad  = (const float*)d_in[11];
    const float* c1_le  = (const float*)d_in[12];
    const float* c1_ae  = (const float*)d_in[13];
    const float* c1_b   = (const float*)d_in[14];
    const float* c2_lin = (const float*)d_in[15];
    const float* c2_as  = (const float*)d_in[16];
    const float* c2_ad  = (const float*)d_in[17];
    const float* c2_le  = (const float*)d_in[18];
    const float* c2_ae  = (const float*)d_in[19];
    const float* c2_b   = (const float*)d_in[20];
    const float* n1_g   = (const float*)d_in[21];
    const float* n1_b   = (const float*)d_in[22];
    const float* n2_g   = (const float*)d_in[23];
    const float* n2_b   = (const float*)d_in[24];
    const float* jk_w   = (const float*)d_in[25];
    const float* jk_b   = (const float*)d_in[26];
    const float* cls_w  = (const float*)d_in[27];
    const float* cls_b  = (const float*)d_in[28];
    float* out = (float*)d_out;

    k_fused1<<<B_HIST+B_CW+1+B_NODE1,256>>>(ei, c1_le, c1_ae, c2_le, c2_ae,
                                            cls_w, cls_b, jk_w, jk_b,
                                            x, proj_w, proj_b, c1_lin, c1_as, c1_ad);
    k_scanab<<<98,512>>>();
    k_scanc<<<98,512>>>();
    k_edge<<<(QSTRIDE+255)/256,256>>>(ea, ei, ee_w1, ee_b1, ee_w2, ee_b2);
    k_gat<<<(NN+15)/16,512>>>(c1_b, n1_g, n1_b, 0, out);
    k_node2<<<(NN+127)/128,256>>>(c2_lin, c2_as, c2_ad);
    k_gat<<<(NN+15)/16,512>>>(c2_b, n2_g, n2_b, 1, out);
}

// round 13
// speedup vs baseline: 1.2270x; 1.0243x over previous
#include <cuda_runtime.h>
#include <cuda_fp16.h>
#include <math.h>

#define NN 50000
#define EE 800000

// ---------------- scratch (device globals; zero-initialized at load) ----------------
__device__ float  g_sae1[EE*4];   // a_edge (conv1) in CSR order
__device__ float  g_sae2[EE*4];   // a_edge (conv2) in CSR order
__device__ int    g_ssrc[EE];     // src node in CSR order
__device__ int    g_cnt[NN];      // invariant: zero at entry (scanc re-zeroes)
__device__ int    g_cur[NN];
__device__ int    g_rowptr[NN+1];
__device__ int    g_part[128];
__device__ int    g_scancnt;      // invariant: zero at entry (last block re-zeroes)
__device__ float  g_h0[NN*128];
__device__ float  g_h1[NN*128];
__device__ float  g_h2[NN*128];
__device__ __half g_xsh[NN*128];  // fp16 transformed features (gather source)
__device__ float  g_asrc[NN*4];
__device__ float  g_adst[NN*4];
__device__ float  g_M[32];        // [conv*16 + j*4 + h]
__device__ float  g_CW[5*384];    // collapsed classifier: cls_w @ jk_w
__device__ float  g_cb2[5];       // collapsed bias

// ---------------- helpers ----------------
__device__ __forceinline__ unsigned long long pack2(float x){
    unsigned long long r;
    unsigned int u = __float_as_uint(x);
    asm("mov.b64 %0, {%1, %1};" : "=l"(r) : "r"(u));
    return r;
}
__device__ __forceinline__ void fma2(unsigned long long& acc,
                                     unsigned long long a, unsigned long long b){
    asm("fma.rn.f32x2 %0, %1, %2, %0;" : "+l"(acc) : "l"(a), "l"(b));
}
__device__ __forceinline__ float lo2(unsigned long long v){
    unsigned int a, b;
    asm("mov.b64 {%0, %1}, %2;" : "=r"(a), "=r"(b) : "l"(v));
    return __uint_as_float(a);
}
__device__ __forceinline__ float hi2(unsigned long long v){
    unsigned int a, b;
    asm("mov.b64 {%0, %1}, %2;" : "=r"(a), "=r"(b) : "l"(v));
    return __uint_as_float(b);
}
__device__ __forceinline__ unsigned h2u(__half2 h){
    return *reinterpret_cast<unsigned*>(&h);
}

// ============ launch 1: hist + CW-prep + M-prep + node1, fused ============
#define B_HIST 782
#define B_CW   241
#define B_NODE1 1563

__global__ void __launch_bounds__(256) k_fused1(
        const int* __restrict__ ei,
        const float* __restrict__ le1, const float* __restrict__ ae1,
        const float* __restrict__ le2, const float* __restrict__ ae2,
        const float* __restrict__ cw,  const float* __restrict__ cb,
        const float* __restrict__ jkw, const float* __restrict__ jkb,
        const float* __restrict__ x,
        const float* __restrict__ pw, const float* __restrict__ pb,
        const float* __restrict__ lw,
        const float* __restrict__ asv, const float* __restrict__ adv){
    int b = blockIdx.x;
    if (b < B_HIST){
        int t = b*256 + threadIdx.x;
        if (t < EE/4){
            int4 d4 = ((const int4*)(ei+EE))[t];
            atomicAdd(&g_cnt[d4.x], 1);
            atomicAdd(&g_cnt[d4.y], 1);
            atomicAdd(&g_cnt[d4.z], 1);
            atomicAdd(&g_cnt[d4.w], 1);
        }
        return;
    }
    if (b < B_HIST + B_CW){
        int w = (b-B_HIST)*8 + (threadIdx.x >> 5);
        int lane = threadIdx.x & 31;
        if (w >= 5*385) return;
        int c = w / 385, j = w % 385;
        float4 a = *(const float4*)&cw[c*128 + lane*4];
        int d = lane*4;
        float s;
        if (j < 384){
            s = a.x*jkw[(d+0)*384+j] + a.y*jkw[(d+1)*384+j]
              + a.z*jkw[(d+2)*384+j] + a.w*jkw[(d+3)*384+j];
        } else {
            float4 bb = *(const float4*)&jkb[d];
            s = a.x*bb.x + a.y*bb.y + a.z*bb.z + a.w*bb.w;
        }
        #pragma unroll
        for (int o=16;o>0;o>>=1) s += __shfl_xor_sync(0xffffffffu, s, o);
        if (lane == 0){
            if (j < 384) g_CW[c*384+j] = s;
            else         g_cb2[c] = s + cb[c];
        }
        return;
    }
    if (b == B_HIST + B_CW){
        int t = threadIdx.x;
        if (t < 32){
            int which = t >> 4, j = (t >> 2) & 3, h = t & 3;
            const float* le = which ? le2 : le1;
            const float* ae = which ? ae2 : ae1;
            float s = 0.f;
            for (int c = 0; c < 32; c++)
                s += le[(h*32+c)*4 + j] * ae[h*32+c];
            g_M[which*16 + j*4 + h] = s;
        }
        return;
    }
    // ---- node1: two independent 128-thread halves ----
    __shared__ __align__(16) float sx[2][16*20];
    int tid = threadIdx.x;
    int sub = tid >> 7, stid = tid & 127;
    int n0 = (b - (B_HIST+B_CW+1))*32 + sub*16;
    float attS = asv[stid], attD = adv[stid], pbd = pb[stid];
    float wp[16], wl[16];
    #pragma unroll
    for (int q=0;q<4;q++){
        float4 a = *(const float4*)&pw[stid*16 + q*4];
        wp[q*4+0]=a.x; wp[q*4+1]=a.y; wp[q*4+2]=a.z; wp[q*4+3]=a.w;
        float4 bb = *(const float4*)&lw[stid*16 + q*4];
        wl[q*4+0]=bb.x; wl[q*4+1]=bb.y; wl[q*4+2]=bb.z; wl[q*4+3]=bb.w;
    }
    for (int i=stid;i<256;i+=128){
        int n=i>>4, k=i&15;
        int node=n0+n;
        sx[sub][n*20+k] = (node<NN) ? x[node*16+k] : 0.f;
    }
    __syncthreads();
    float acc0[16], acc1[16];
    #pragma unroll
    for (int n=0;n<16;n++){ acc0[n]=pbd; acc1[n]=0.f; }
    #pragma unroll
    for (int n=0;n<16;n++){
        float4 x0 = *(const float4*)&sx[sub][n*20];
        float4 x1 = *(const float4*)&sx[sub][n*20+4];
        float4 x2 = *(const float4*)&sx[sub][n*20+8];
        float4 x3 = *(const float4*)&sx[sub][n*20+12];
        float xv[16] = {x0.x,x0.y,x0.z,x0.w, x1.x,x1.y,x1.z,x1.w,
                        x2.x,x2.y,x2.z,x2.w, x3.x,x3.y,x3.z,x3.w};
        #pragma unroll
        for (int k=0;k<16;k++){
            acc0[n] = fmaf(xv[k], wp[k], acc0[n]);
            acc1[n] = fmaf(xv[k], wl[k], acc1[n]);
        }
    }
    int lane = stid&31, h = stid>>5;
    for (int n=0;n<16;n++){
        int node=n0+n;
        if (node>=NN) break;
        g_h0[node*128+stid]  = acc0[n];
        g_xsh[node*128+stid] = __float2half(acc1[n]);
        float s = acc1[n]*attS, dd = acc1[n]*attD;
        #pragma unroll
        for (int o=16;o>0;o>>=1){
            s  += __shfl_down_sync(0xffffffffu, s, o);
            dd += __shfl_down_sync(0xffffffffu, dd, o);
        }
        if (lane==0){ g_asrc[node*4+h]=s; g_adst[node*4+h]=dd; }
    }
}

// ---------------- scan: block sums + last-block scans partials ----------------
__global__ void __launch_bounds__(512) k_scanab(){
    __shared__ int sred[16];
    __shared__ int amlast;
    __shared__ int sb[128];
    int t = blockIdx.x*512 + threadIdx.x;
    int v = (t < NN) ? g_cnt[t] : 0;
    #pragma unroll
    for (int o=16;o>0;o>>=1) v += __shfl_xor_sync(0xffffffffu, v, o);
    int lane = threadIdx.x & 31, wid = threadIdx.x >> 5;
    if (lane == 0) sred[wid] = v;
    __syncthreads();
    if (threadIdx.x < 16){
        v = sred[threadIdx.x];
        #pragma unroll
        for (int o=8;o>0;o>>=1) v += __shfl_xor_sync(0xffffu, v, o);
    }
    if (threadIdx.x == 0){
        g_part[blockIdx.x] = v;
        __threadfence();
        int n = atomicAdd(&g_scancnt, 1);
        int last = (n == 97);
        if (last) g_scancnt = 0;      // restore zero-invariant
        amlast = last;
    }
    __syncthreads();
    if (amlast){
        __threadfence();
        int tt = threadIdx.x;
        int vv = 0;
        if (tt < 128){
            vv = (tt < 98) ? g_part[tt] : 0;
            sb[tt] = vv;
        }
        __syncthreads();
        for (int off=1; off<128; off<<=1){
            int u = (tt >= off && tt < 128) ? sb[tt-off] : 0;
            __syncthreads();
            if (tt < 128) sb[tt] += u;
            __syncthreads();
        }
        if (tt < 98) g_part[tt] = sb[tt] - vv;   // exclusive
    }
}

__global__ void __launch_bounds__(512) k_scanc(){
    __shared__ int s[512];
    int t = blockIdx.x*512 + threadIdx.x;
    int v = (t < NN) ? g_cnt[t] : 0;
    s[threadIdx.x] = v;
    __syncthreads();
    for (int off=1; off<512; off<<=1){
        int u = (threadIdx.x >= off) ? s[threadIdx.x-off] : 0;
        __syncthreads();
        s[threadIdx.x] += u;
        __syncthreads();
    }
    int excl = s[threadIdx.x] - v + g_part[blockIdx.x];
    if (t < NN){
        g_rowptr[t] = excl;
        g_cur[t]    = excl;
        g_cnt[t]    = 0;                // restore zero-invariant
        if (t == NN-1) g_rowptr[NN] = excl + v;
    }
}

// ---------------- edge encoder: 2 edges/thread, WM-folded, coalesced, high-occ ----------------
#define QSTRIDE2 400000   // EE/2
__global__ void __launch_bounds__(256) k_edge(
        const float* __restrict__ ea, const int* __restrict__ ei,
        const float* __restrict__ w1, const float* __restrict__ b1,
        const float* __restrict__ w2, const float* __restrict__ b2){
    __shared__ __align__(16) float sw1[256];
    __shared__ float sb1[32];
    __shared__ __align__(16) float sWM1[128];  // [c][h]
    __shared__ __align__(16) float sWM2[128];
    __shared__ float sR0[8];
    int tid = threadIdx.x;
    if (tid < 256) sw1[tid] = w1[tid];
    if (tid < 32)  sb1[tid] = b1[tid];
    if (tid < 128){
        int c = tid >> 2, h = tid & 3;
        float s1 = 0.f, s2 = 0.f;
        #pragma unroll
        for (int j=0;j<4;j++){
            float wv = w2[j*32+c];
            s1 = fmaf(wv, g_M[j*4+h],    s1);
            s2 = fmaf(wv, g_M[16+j*4+h], s2);
        }
        sWM1[c*4+h] = s1;
        sWM2[c*4+h] = s2;
    }
    if (tid >= 128 && tid < 136){
        int which = (tid-128) >> 2, h = tid & 3;
        float s = 0.f;
        #pragma unroll
        for (int j=0;j<4;j++) s = fmaf(b2[j], g_M[which*16+j*4+h], s);
        sR0[tid-128] = s;
    }
    __syncthreads();
    int gid = blockIdx.x*256 + tid;
    if (gid >= QSTRIDE2) return;
    // 2 edges: gid, gid+QSTRIDE2 — each fully coalesced across lanes
    float4 A[2][2];
    #pragma unroll
    for (int q=0;q<2;q++){
        int e = gid + q*QSTRIDE2;
        A[q][0] = ((const float4*)ea)[e*2];
        A[q][1] = ((const float4*)ea)[e*2+1];
    }
    float4 R10 = *(const float4*)&sR0[0];
    float4 R20 = *(const float4*)&sR0[4];
    float4 r1[2], r2[2];
    #pragma unroll
    for (int q=0;q<2;q++){ r1[q]=R10; r2[q]=R20; }
    #pragma unroll
    for (int c=0;c<32;c++){
        float4 wa = *(const float4*)&sw1[c*8];
        float4 wb = *(const float4*)&sw1[c*8+4];
        float bc  = sb1[c];
        float4 m1 = *(const float4*)&sWM1[c*4];
        float4 m2 = *(const float4*)&sWM2[c*4];
        #pragma unroll
        for (int q=0;q<2;q++){
            float hv = bc;
            hv = fmaf(wa.x, A[q][0].x, hv); hv = fmaf(wa.y, A[q][0].y, hv);
            hv = fmaf(wa.z, A[q][0].z, hv); hv = fmaf(wa.w, A[q][0].w, hv);
            hv = fmaf(wb.x, A[q][1].x, hv); hv = fmaf(wb.y, A[q][1].y, hv);
            hv = fmaf(wb.z, A[q][1].z, hv); hv = fmaf(wb.w, A[q][1].w, hv);
            hv = fmaxf(hv, 0.f);
            r1[q].x = fmaf(m1.x, hv, r1[q].x);
            r1[q].y = fmaf(m1.y, hv, r1[q].y);
            r1[q].z = fmaf(m1.z, hv, r1[q].z);
            r1[q].w = fmaf(m1.w, hv, r1[q].w);
            r2[q].x = fmaf(m2.x, hv, r2[q].x);
            r2[q].y = fmaf(m2.y, hv, r2[q].y);
            r2[q].z = fmaf(m2.z, hv, r2[q].z);
            r2[q].w = fmaf(m2.w, hv, r2[q].w);
        }
    }
    #pragma unroll
    for (int q=0;q<2;q++){
        int e = gid + q*QSTRIDE2;
        int srcn = ei[e], d = ei[EE+e];
        int pos = atomicAdd(&g_cur[d], 1);
        g_ssrc[pos] = srcn;
        ((float4*)g_sae1)[pos] = r1[q];
        ((float4*)g_sae2)[pos] = r2[q];
    }
}

// ---------------- fused GAT conv (HFMA2 gather) + (conv2) classifier/log_softmax ----------------
__global__ void __launch_bounds__(512) k_gat(const float* __restrict__ bias,
                      const float* __restrict__ gam,
                      const float* __restrict__ bet, int conv,
                      float* __restrict__ out){
    __shared__ float2 sp[16][132];   // [warp][h*33 + j]: (src byte-offset, half2(w))
    __shared__ float sCW[1920];
    __shared__ float sCB[5];
    int tid = threadIdx.x;
    if (conv){
        for (int i=tid;i<1920;i+=512) sCW[i] = g_CW[i];
        if (tid < 5) sCB[tid] = g_cb2[tid];
    }
    __syncthreads();
    int wid = tid >> 5, lane = tid & 31;
    int node = blockIdx.x*16 + wid;
    if (node >= NN) return;
    int h = lane >> 3;
    const float4* __restrict__ sae   = (const float4*)(conv ? g_sae2 : g_sae1);
    const float4* __restrict__ asrc4 = (const float4*)g_asrc;
    const char*   xbase = ((const char*)g_xsh) + lane*8;
    float4 ad = ((const float4*)g_adst)[node];
    int beg = g_rowptr[node], end = g_rowptr[node+1];
    float4 den = make_float4(0.f,0.f,0.f,0.f);
    __half2 acc0 = __float2half2_rn(0.f);
    __half2 acc1 = __float2half2_rn(0.f);
    for (int base = beg; base < end; base += 32){
        int idx = base + lane;
        bool v = idx < end;
        int s = g_ssrc[v ? idx : end-1];
        float4 w = make_float4(0.f,0.f,0.f,0.f);
        if (v){
            float4 ae = sae[idx];
            float4 as = asrc4[s];
            float ax = as.x+ad.x+ae.x; ax = ax>0.f?ax:0.2f*ax;
            float ay = as.y+ad.y+ae.y; ay = ay>0.f?ay:0.2f*ay;
            float az = as.z+ad.z+ae.z; az = az>0.f?az:0.2f*az;
            float aw = as.w+ad.w+ae.w; aw = aw>0.f?aw:0.2f*aw;
            w = make_float4(__expf(ax), __expf(ay), __expf(az), __expf(aw));
        }
        den.x += w.x; den.y += w.y; den.z += w.z; den.w += w.w;
        float so = __uint_as_float((unsigned)s * 256u);   // byte offset of fp16 row
        __syncwarp();
        sp[wid][lane]       = make_float2(so, __uint_as_float(h2u(__float2half2_rn(w.x))));
        sp[wid][33 + lane]  = make_float2(so, __uint_as_float(h2u(__float2half2_rn(w.y))));
        sp[wid][66 + lane]  = make_float2(so, __uint_as_float(h2u(__float2half2_rn(w.z))));
        sp[wid][99 + lane]  = make_float2(so, __uint_as_float(h2u(__float2half2_rn(w.w))));
        __syncwarp();
        int cnt = end - base; if (cnt > 32) cnt = 32;
        const float2* hp2 = &sp[wid][h*33];
        for (int c = 0; c < cnt; c += 8){
            #pragma unroll
            for (int j = 0; j < 8; j++){
                float2 e2 = hp2[c+j];
                uint2 xr = *(const uint2*)(xbase + __float_as_uint(e2.x));
                unsigned wb = __float_as_uint(e2.y);
                __half2 wh = *reinterpret_cast<__half2*>(&wb);
                acc0 = __hfma2(*reinterpret_cast<__half2*>(&xr.x), wh, acc0);
                acc1 = __hfma2(*reinterpret_cast<__half2*>(&xr.y), wh, acc1);
            }
        }
    }
    #pragma unroll
    for (int o=16;o>0;o>>=1){
        den.x += __shfl_xor_sync(0xffffffffu, den.x, o);
        den.y += __shfl_xor_sync(0xffffffffu, den.y, o);
        den.z += __shfl_xor_sync(0xffffffffu, den.z, o);
        den.w += __shfl_xor_sync(0xffffffffu, den.w, o);
    }
    float dh = (h==0)?den.x:(h==1)?den.y:(h==2)?den.z:den.w;
    float inv = 1.f/(dh + 1e-16f);
    float2 f0 = __half22float2(acc0);
    float2 f1 = __half22float2(acc1);
    const float* hp = conv ? g_h1 : g_h0;
    float*       ho = conv ? g_h2 : g_h1;
    float4 hv = ((const float4*)hp)[node*32+lane];
    float4 bv = *(const float4*)&bias[lane*4];
    float4 r;
    r.x = f0.x*inv + bv.x; r.x = (r.x>0.f)?r.x:(__expf(r.x)-1.f); r.x += hv.x;
    r.y = f0.y*inv + bv.y; r.y = (r.y>0.f)?r.y:(__expf(r.y)-1.f); r.y += hv.y;
    r.z = f1.x*inv + bv.z; r.z = (r.z>0.f)?r.z:(__expf(r.z)-1.f); r.z += hv.z;
    r.w = f1.y*inv + bv.w; r.w = (r.w>0.f)?r.w:(__expf(r.w)-1.f); r.w += hv.w;
    float s1 = r.x+r.y+r.z+r.w;
    float s2 = r.x*r.x + r.y*r.y + r.z*r.z + r.w*r.w;
    #pragma unroll
    for (int o=16;o>0;o>>=1){
        s1 += __shfl_xor_sync(0xffffffffu, s1, o);
        s2 += __shfl_xor_sync(0xffffffffu, s2, o);
    }
    float mu  = s1 * (1.f/128.f);
    float var = s2 * (1.f/128.f) - mu*mu;
    float rs  = rsqrtf(var + 1e-5f);
    float4 gv = *(const float4*)&gam[lane*4];
    float4 be = *(const float4*)&bet[lane*4];
    float4 o4;
    o4.x = (r.x-mu)*rs*gv.x + be.x;
    o4.y = (r.y-mu)*rs*gv.y + be.y;
    o4.z = (r.z-mu)*rs*gv.z + be.z;
    o4.w = (r.w-mu)*rs*gv.w + be.w;
    ((float4*)ho)[node*32+lane] = o4;

    if (conv){
        float4 a0 = ((const float4*)g_h0)[node*32+lane];
        float lg[5];
        #pragma unroll
        for (int c=0;c<5;c++){
            const float* w = &sCW[c*384];
            float4 b0 = *(const float4*)&w[lane*4];
            float4 b1 = *(const float4*)&w[128 + lane*4];
            float4 b2 = *(const float4*)&w[256 + lane*4];
            float p = a0.x*b0.x + a0.y*b0.y + a0.z*b0.z + a0.w*b0.w;
            p = fmaf(hv.x,b1.x, fmaf(hv.y,b1.y, fmaf(hv.z,b1.z, fmaf(hv.w,b1.w, p))));
            p = fmaf(o4.x,b2.x, fmaf(o4.y,b2.y, fmaf(o4.z,b2.z, fmaf(o4.w,b2.w, p))));
            #pragma unroll
            for (int o=16;o>0;o>>=1) p += __shfl_xor_sync(0xffffffffu, p, o);
            lg[c] = p + sCB[c];
        }
        if (lane == 0){
            float m = lg[0];
            #pragma unroll
            for (int c=1;c<5;c++) m = fmaxf(m, lg[c]);
            float s = 0.f;
            #pragma unroll
            for (int c=0;c<5;c++) s += __expf(lg[c]-m);
            float ls = logf(s);
            #pragma unroll
            for (int c=0;c<5;c++) out[node*5+c] = lg[c]-m-ls;
        }
    }
}

// ---------------- conv2 GEMM + fused attention dots (fp16 xs output) ----------------
__global__ void __launch_bounds__(256) k_node2(const float* __restrict__ lin,
                                               const float* __restrict__ asv,
                                               const float* __restrict__ adv){
    __shared__ float sA[16*132];
    __shared__ float sB[16*132];
    int tid = threadIdx.x;
    int tx = tid & 15, ty = tid >> 4;
    int n0 = blockIdx.x*128;
    unsigned long long acc[8][4];
    #pragma unroll
    for (int r=0;r<8;r++)
        #pragma unroll
        for (int p=0;p<4;p++) acc[r][p] = 0ULL;
    for (int kc=0;kc<8;kc++){
        __syncthreads();
        #pragma unroll
        for (int t=tid;t<512;t+=256){
            int r = t>>2, q = t&3;
            int node = n0 + r;
            float4 v = (node<NN) ? *(const float4*)&g_h1[node*128 + kc*16 + q*4]
                                 : make_float4(0.f,0.f,0.f,0.f);
            sA[(q*4+0)*132+r]=v.x; sA[(q*4+1)*132+r]=v.y;
            sA[(q*4+2)*132+r]=v.z; sA[(q*4+3)*132+r]=v.w;
        }
        #pragma unroll
        for (int t=tid;t<512;t+=256){
            int d = t>>2, q = t&3;
            float4 v = *(const float4*)&lin[d*128 + kc*16 + q*4];
            sB[(q*4+0)*132+d]=v.x; sB[(q*4+1)*132+d]=v.y;
            sB[(q*4+2)*132+d]=v.z; sB[(q*4+3)*132+d]=v.w;
        }
        __syncthreads();
        #pragma unroll
        for (int k=0;k<16;k++){
            float4 a0 = *(const float4*)&sA[k*132 + ty*8];
            float4 a1 = *(const float4*)&sA[k*132 + ty*8 + 4];
            ulonglong2 b0 = *(const ulonglong2*)&sB[k*132 + tx*8];
            ulonglong2 b1 = *(const ulonglong2*)&sB[k*132 + tx*8 + 4];
            unsigned long long bp0=b0.x, bp1=b0.y, bp2=b1.x, bp3=b1.y;
            float ar[8] = {a0.x,a0.y,a0.z,a0.w,a1.x,a1.y,a1.z,a1.w};
            #pragma unroll
            for (int r=0;r<8;r++){
                unsigned long long a2 = pack2(ar[r]);
                fma2(acc[r][0], a2, bp0);
                fma2(acc[r][1], a2, bp1);
                fma2(acc[r][2], a2, bp2);
                fma2(acc[r][3], a2, bp3);
            }
        }
    }
    float4 ws0 = *(const float4*)&asv[tx*8];
    float4 ws1 = *(const float4*)&asv[tx*8+4];
    float4 wd0 = *(const float4*)&adv[tx*8];
    float4 wd1 = *(const float4*)&adv[tx*8+4];
    int hh = tx >> 2;
    #pragma unroll
    for (int r=0;r<8;r++){
        int node = n0 + ty*8 + r;
        if (node < NN){
            float f0=lo2(acc[r][0]), f1=hi2(acc[r][0]);
            float f2=lo2(acc[r][1]), f3=hi2(acc[r][1]);
            float f4=lo2(acc[r][2]), f5=hi2(acc[r][2]);
            float f6=lo2(acc[r][3]), f7=hi2(acc[r][3]);
            uint4 st;
            st.x = h2u(__floats2half2_rn(f0, f1));
            st.y = h2u(__floats2half2_rn(f2, f3));
            st.z = h2u(__floats2half2_rn(f4, f5));
            st.w = h2u(__floats2half2_rn(f6, f7));
            *(uint4*)(((char*)g_xsh) + node*256 + tx*16) = st;
            float s = f0*ws0.x + f1*ws0.y + f2*ws0.z + f3*ws0.w
                    + f4*ws1.x + f5*ws1.y + f6*ws1.z + f7*ws1.w;
            float d = f0*wd0.x + f1*wd0.y + f2*wd0.z + f3*wd0.w
                    + f4*wd1.x + f5*wd1.y + f6*wd1.z + f7*wd1.w;
            s += __shfl_xor_sync(0xffffffffu, s, 1);
            s += __shfl_xor_sync(0xffffffffu, s, 2);
            d += __shfl_xor_sync(0xffffffffu, d, 1);
            d += __shfl_xor_sync(0xffffffffu, d, 2);
            if ((tx & 3) == 0){
                g_asrc[node*4+hh] = s;
                g_adst[node*4+hh] = d;
            }
        }
    }
}

// ---------------- launcher ----------------
extern "C" void kernel_launch(void* const* d_in, const int* in_sizes, int n_in,
                              void* d_out, int out_size){
    const float* x      = (const float*)d_in[0];
    const int*   ei     = (const int*)  d_in[1];
    const float* ea     = (const float*)d_in[2];
    const float* ee_w1  = (const float*)d_in[3];
    const float* ee_b1  = (const float*)d_in[4];
    const float* ee_w2  = (const float*)d_in[5];
    const float* ee_b2  = (const float*)d_in[6];
    const float* proj_w = (const float*)d_in[7];
    const float* proj_b = (const float*)d_in[8];
    const float* c1_lin = (const float*)d_in[9];
    const float* c1_as  = (const float*)d_in[10];
    const float* c1_ad  = (const float*)d_in[11];
    const float* c1_le  = (const float*)d_in[12];
    const float* c1_ae  = (const float*)d_in[13];
    const float* c1_b   = (const float*)d_in[14];
    const float* c2_lin = (const float*)d_in[15];
    const float* c2_as  = (const float*)d_in[16];
    const float* c2_ad  = (const float*)d_in[17];
    const float* c2_le  = (const float*)d_in[18];
    const float* c2_ae  = (const float*)d_in[19];
    const float* c2_b   = (const float*)d_in[20];
    const float* n1_g   = (const float*)d_in[21];
    const float* n1_b   = (const float*)d_in[22];
    const float* n2_g   = (const float*)d_in[23];
    const float* n2_b   = (const float*)d_in[24];
    const float* jk_w   = (const float*)d_in[25];
    const float* jk_b   = (const float*)d_in[26];
    const float* cls_w  = (const float*)d_in[27];
    const float* cls_b  = (const float*)d_in[28];
    float* out = (float*)d_out;

    k_fused1<<<B_HIST+B_CW+1+B_NODE1,256>>>(ei, c1_le, c1_ae, c2_le, c2_ae,
                                            cls_w, cls_b, jk_w, jk_b,
                                            x, proj_w, proj_b, c1_lin, c1_as, c1_ad);
    k_scanab<<<98,512>>>();
    k_scanc<<<98,512>>>();
    k_edge<<<(QSTRIDE2+255)/256,256>>>(ea, ei, ee_w1, ee_b1, ee_w2, ee_b2);
    k_gat<<<(NN+15)/16,512>>>(c1_b, n1_g, n1_b, 0, out);
    k_node2<<<(NN+127)/128,256>>>(c2_lin, c2_as, c2_ad);
    k_gat<<<(NN+15)/16,512>>>(c2_b, n2_g, n2_b, 1, out);
}

// round 14
// speedup vs baseline: 1.3002x; 1.0597x over previous
#include <cuda_runtime.h>
#include <cuda_fp16.h>
#include <math.h>

#define NN 50000
#define EE 800000

// ---------------- scratch (device globals; zero-initialized at load) ----------------
__device__ float  g_sae1[EE*4];   // a_edge (conv1) in CSR order
__device__ float  g_sae2[EE*4];   // a_edge (conv2) in CSR order
__device__ int    g_ssrc[EE];     // src node in CSR order
__device__ int    g_cnt[NN];      // invariant: zero at entry (scanc re-zeroes)
__device__ int    g_cur[NN];
__device__ int    g_rowptr[NN+1];
__device__ int    g_part[128];
__device__ int    g_scancnt;      // invariant: zero at entry (last block re-zeroes)
__device__ float  g_h0[NN*128];
__device__ float  g_h1[NN*128];
__device__ float  g_h2[NN*128];
__device__ __half g_xsh[NN*128];  // fp16 transformed features (gather source)
__device__ float  g_asrc[NN*4];
__device__ float  g_adst[NN*4];
__device__ float  g_M[32];        // [conv*16 + j*4 + h]
__device__ float  g_CW[5*384];    // collapsed classifier: cls_w @ jk_w
__device__ float  g_cb2[5];       // collapsed bias

// ---------------- helpers ----------------
__device__ __forceinline__ unsigned long long pack2(float x){
    unsigned long long r;
    unsigned int u = __float_as_uint(x);
    asm("mov.b64 %0, {%1, %1};" : "=l"(r) : "r"(u));
    return r;
}
__device__ __forceinline__ void fma2(unsigned long long& acc,
                                     unsigned long long a, unsigned long long b){
    asm("fma.rn.f32x2 %0, %1, %2, %0;" : "+l"(acc) : "l"(a), "l"(b));
}
__device__ __forceinline__ float lo2(unsigned long long v){
    unsigned int a, b;
    asm("mov.b64 {%0, %1}, %2;" : "=r"(a), "=r"(b) : "l"(v));
    return __uint_as_float(a);
}
__device__ __forceinline__ float hi2(unsigned long long v){
    unsigned int a, b;
    asm("mov.b64 {%0, %1}, %2;" : "=r"(a), "=r"(b) : "l"(v));
    return __uint_as_float(b);
}
__device__ __forceinline__ unsigned h2u(__half2 h){
    return *reinterpret_cast<unsigned*>(&h);
}

// ============ launch 1: hist + CW-prep + M-prep + node1, fused ============
#define B_HIST 782
#define B_CW   241
#define B_NODE1 1563

__global__ void __launch_bounds__(256) k_fused1(
        const int* __restrict__ ei,
        const float* __restrict__ le1, const float* __restrict__ ae1,
        const float* __restrict__ le2, const float* __restrict__ ae2,
        const float* __restrict__ cw,  const float* __restrict__ cb,
        const float* __restrict__ jkw, const float* __restrict__ jkb,
        const float* __restrict__ x,
        const float* __restrict__ pw, const float* __restrict__ pb,
        const float* __restrict__ lw,
        const float* __restrict__ asv, const float* __restrict__ adv){
    int b = blockIdx.x;
    if (b < B_HIST){
        int t = b*256 + threadIdx.x;
        if (t < EE/4){
            int4 d4 = ((const int4*)(ei+EE))[t];
            atomicAdd(&g_cnt[d4.x], 1);
            atomicAdd(&g_cnt[d4.y], 1);
            atomicAdd(&g_cnt[d4.z], 1);
            atomicAdd(&g_cnt[d4.w], 1);
        }
        return;
    }
    if (b < B_HIST + B_CW){
        int w = (b-B_HIST)*8 + (threadIdx.x >> 5);
        int lane = threadIdx.x & 31;
        if (w >= 5*385) return;
        int c = w / 385, j = w % 385;
        float4 a = *(const float4*)&cw[c*128 + lane*4];
        int d = lane*4;
        float s;
        if (j < 384){
            s = a.x*jkw[(d+0)*384+j] + a.y*jkw[(d+1)*384+j]
              + a.z*jkw[(d+2)*384+j] + a.w*jkw[(d+3)*384+j];
        } else {
            float4 bb = *(const float4*)&jkb[d];
            s = a.x*bb.x + a.y*bb.y + a.z*bb.z + a.w*bb.w;
        }
        #pragma unroll
        for (int o=16;o>0;o>>=1) s += __shfl_xor_sync(0xffffffffu, s, o);
        if (lane == 0){
            if (j < 384) g_CW[c*384+j] = s;
            else         g_cb2[c] = s + cb[c];
        }
        return;
    }
    if (b == B_HIST + B_CW){
        int t = threadIdx.x;
        if (t < 32){
            int which = t >> 4, j = (t >> 2) & 3, h = t & 3;
            const float* le = which ? le2 : le1;
            const float* ae = which ? ae2 : ae1;
            float s = 0.f;
            for (int c = 0; c < 32; c++)
                s += le[(h*32+c)*4 + j] * ae[h*32+c];
            g_M[which*16 + j*4 + h] = s;
        }
        return;
    }
    // ---- node1: two independent 128-thread halves ----
    __shared__ __align__(16) float sx[2][16*20];
    int tid = threadIdx.x;
    int sub = tid >> 7, stid = tid & 127;
    int n0 = (b - (B_HIST+B_CW+1))*32 + sub*16;
    float attS = asv[stid], attD = adv[stid], pbd = pb[stid];
    float wp[16], wl[16];
    #pragma unroll
    for (int q=0;q<4;q++){
        float4 a = *(const float4*)&pw[stid*16 + q*4];
        wp[q*4+0]=a.x; wp[q*4+1]=a.y; wp[q*4+2]=a.z; wp[q*4+3]=a.w;
        float4 bb = *(const float4*)&lw[stid*16 + q*4];
        wl[q*4+0]=bb.x; wl[q*4+1]=bb.y; wl[q*4+2]=bb.z; wl[q*4+3]=bb.w;
    }
    for (int i=stid;i<256;i+=128){
        int n=i>>4, k=i&15;
        int node=n0+n;
        sx[sub][n*20+k] = (node<NN) ? x[node*16+k] : 0.f;
    }
    __syncthreads();
    float acc0[16], acc1[16];
    #pragma unroll
    for (int n=0;n<16;n++){ acc0[n]=pbd; acc1[n]=0.f; }
    #pragma unroll
    for (int n=0;n<16;n++){
        float4 x0 = *(const float4*)&sx[sub][n*20];
        float4 x1 = *(const float4*)&sx[sub][n*20+4];
        float4 x2 = *(const float4*)&sx[sub][n*20+8];
        float4 x3 = *(const float4*)&sx[sub][n*20+12];
        float xv[16] = {x0.x,x0.y,x0.z,x0.w, x1.x,x1.y,x1.z,x1.w,
                        x2.x,x2.y,x2.z,x2.w, x3.x,x3.y,x3.z,x3.w};
        #pragma unroll
        for (int k=0;k<16;k++){
            acc0[n] = fmaf(xv[k], wp[k], acc0[n]);
            acc1[n] = fmaf(xv[k], wl[k], acc1[n]);
        }
    }
    int lane = stid&31, h = stid>>5;
    for (int n=0;n<16;n++){
        int node=n0+n;
        if (node>=NN) break;
        g_h0[node*128+stid]  = acc0[n];
        g_xsh[node*128+stid] = __float2half(acc1[n]);
        float s = acc1[n]*attS, dd = acc1[n]*attD;
        #pragma unroll
        for (int o=16;o>0;o>>=1){
            s  += __shfl_down_sync(0xffffffffu, s, o);
            dd += __shfl_down_sync(0xffffffffu, dd, o);
        }
        if (lane==0){ g_asrc[node*4+h]=s; g_adst[node*4+h]=dd; }
    }
}

// ---------------- scan: block sums + last-block scans partials ----------------
__global__ void __launch_bounds__(512) k_scanab(){
    __shared__ int sred[16];
    __shared__ int amlast;
    __shared__ int sb[128];
    int t = blockIdx.x*512 + threadIdx.x;
    int v = (t < NN) ? g_cnt[t] : 0;
    #pragma unroll
    for (int o=16;o>0;o>>=1) v += __shfl_xor_sync(0xffffffffu, v, o);
    int lane = threadIdx.x & 31, wid = threadIdx.x >> 5;
    if (lane == 0) sred[wid] = v;
    __syncthreads();
    if (threadIdx.x < 16){
        v = sred[threadIdx.x];
        #pragma unroll
        for (int o=8;o>0;o>>=1) v += __shfl_xor_sync(0xffffu, v, o);
    }
    if (threadIdx.x == 0){
        g_part[blockIdx.x] = v;
        __threadfence();
        int n = atomicAdd(&g_scancnt, 1);
        int last = (n == 97);
        if (last) g_scancnt = 0;      // restore zero-invariant
        amlast = last;
    }
    __syncthreads();
    if (amlast){
        __threadfence();
        int tt = threadIdx.x;
        int vv = 0;
        if (tt < 128){
            vv = (tt < 98) ? g_part[tt] : 0;
            sb[tt] = vv;
        }
        __syncthreads();
        for (int off=1; off<128; off<<=1){
            int u = (tt >= off && tt < 128) ? sb[tt-off] : 0;
            __syncthreads();
            if (tt < 128) sb[tt] += u;
            __syncthreads();
        }
        if (tt < 98) g_part[tt] = sb[tt] - vv;   // exclusive
    }
}

__global__ void __launch_bounds__(512) k_scanc(){
    __shared__ int s[512];
    int t = blockIdx.x*512 + threadIdx.x;
    int v = (t < NN) ? g_cnt[t] : 0;
    s[threadIdx.x] = v;
    __syncthreads();
    for (int off=1; off<512; off<<=1){
        int u = (threadIdx.x >= off) ? s[threadIdx.x-off] : 0;
        __syncthreads();
        s[threadIdx.x] += u;
        __syncthreads();
    }
    int excl = s[threadIdx.x] - v + g_part[blockIdx.x];
    if (t < NN){
        g_rowptr[t] = excl;
        g_cur[t]    = excl;
        g_cnt[t]    = 0;                // restore zero-invariant
        if (t == NN-1) g_rowptr[NN] = excl + v;
    }
}

// ---------------- edge encoder: 2 edges/thread, WM-folded, coalesced (R13-proven) ----------------
#define QSTRIDE2 400000   // EE/2
__global__ void __launch_bounds__(256) k_edge(
        const float* __restrict__ ea, const int* __restrict__ ei,
        const float* __restrict__ w1, const float* __restrict__ b1,
        const float* __restrict__ w2, const float* __restrict__ b2){
    __shared__ __align__(16) float sw1[256];
    __shared__ float sb1[32];
    __shared__ __align__(16) float sWM1[128];  // [c][h]
    __shared__ __align__(16) float sWM2[128];
    __shared__ float sR0[8];
    int tid = threadIdx.x;
    if (tid < 256) sw1[tid] = w1[tid];
    if (tid < 32)  sb1[tid] = b1[tid];
    if (tid < 128){
        int c = tid >> 2, h = tid & 3;
        float s1 = 0.f, s2 = 0.f;
        #pragma unroll
        for (int j=0;j<4;j++){
            float wv = w2[j*32+c];
            s1 = fmaf(wv, g_M[j*4+h],    s1);
            s2 = fmaf(wv, g_M[16+j*4+h], s2);
        }
        sWM1[c*4+h] = s1;
        sWM2[c*4+h] = s2;
    }
    if (tid >= 128 && tid < 136){
        int which = (tid-128) >> 2, h = tid & 3;
        float s = 0.f;
        #pragma unroll
        for (int j=0;j<4;j++) s = fmaf(b2[j], g_M[which*16+j*4+h], s);
        sR0[tid-128] = s;
    }
    __syncthreads();
    int gid = blockIdx.x*256 + tid;
    if (gid >= QSTRIDE2) return;
    float4 A[2][2];
    #pragma unroll
    for (int q=0;q<2;q++){
        int e = gid + q*QSTRIDE2;
        A[q][0] = ((const float4*)ea)[e*2];
        A[q][1] = ((const float4*)ea)[e*2+1];
    }
    float4 R10 = *(const float4*)&sR0[0];
    float4 R20 = *(const float4*)&sR0[4];
    float4 r1[2], r2[2];
    #pragma unroll
    for (int q=0;q<2;q++){ r1[q]=R10; r2[q]=R20; }
    #pragma unroll
    for (int c=0;c<32;c++){
        float4 wa = *(const float4*)&sw1[c*8];
        float4 wb = *(const float4*)&sw1[c*8+4];
        float bc  = sb1[c];
        float4 m1 = *(const float4*)&sWM1[c*4];
        float4 m2 = *(const float4*)&sWM2[c*4];
        #pragma unroll
        for (int q=0;q<2;q++){
            float hv = bc;
            hv = fmaf(wa.x, A[q][0].x, hv); hv = fmaf(wa.y, A[q][0].y, hv);
            hv = fmaf(wa.z, A[q][0].z, hv); hv = fmaf(wa.w, A[q][0].w, hv);
            hv = fmaf(wb.x, A[q][1].x, hv); hv = fmaf(wb.y, A[q][1].y, hv);
            hv = fmaf(wb.z, A[q][1].z, hv); hv = fmaf(wb.w, A[q][1].w, hv);
            hv = fmaxf(hv, 0.f);
            r1[q].x = fmaf(m1.x, hv, r1[q].x);
            r1[q].y = fmaf(m1.y, hv, r1[q].y);
            r1[q].z = fmaf(m1.z, hv, r1[q].z);
            r1[q].w = fmaf(m1.w, hv, r1[q].w);
            r2[q].x = fmaf(m2.x, hv, r2[q].x);
            r2[q].y = fmaf(m2.y, hv, r2[q].y);
            r2[q].z = fmaf(m2.z, hv, r2[q].z);
            r2[q].w = fmaf(m2.w, hv, r2[q].w);
        }
    }
    #pragma unroll
    for (int q=0;q<2;q++){
        int e = gid + q*QSTRIDE2;
        int srcn = ei[e], d = ei[EE+e];
        int pos = atomicAdd(&g_cur[d], 1);
        g_ssrc[pos] = srcn;
        ((float4*)g_sae1)[pos] = r1[q];
        ((float4*)g_sae2)[pos] = r2[q];
    }
}

// ---------------- fused GAT conv: 2 nodes/warp, HFMA2 gather + classifier ----------------
__global__ void __launch_bounds__(512) k_gat(const float* __restrict__ bias,
                      const float* __restrict__ gam,
                      const float* __restrict__ bet, int conv,
                      float* __restrict__ out){
    __shared__ float2 sp[16][2][68];   // [warp][half][h*17 + j]
    __shared__ float sCW[1920];
    __shared__ float sCB[5];
    int tid = threadIdx.x;
    if (conv){
        for (int i=tid;i<1920;i+=512) sCW[i] = g_CW[i];
        if (tid < 5) sCB[tid] = g_cb2[tid];
    }
    __syncthreads();
    int wid = tid >> 5, lane = tid & 31;
    int half = lane >> 4, sub = lane & 15;
    int node = blockIdx.x*32 + wid*2 + half;
    bool nv = node < NN;
    int h = sub >> 2;                      // head of this lane's 8 dims
    const float4* __restrict__ sae   = (const float4*)(conv ? g_sae2 : g_sae1);
    const float4* __restrict__ asrc4 = (const float4*)g_asrc;
    const char*   xbase = ((const char*)g_xsh) + sub*16;   // 8 halves per lane
    float4 ad = nv ? ((const float4*)g_adst)[node] : make_float4(0.f,0.f,0.f,0.f);
    int beg = nv ? g_rowptr[node]   : 0;
    int end = nv ? g_rowptr[node+1] : 0;
    int cnt = end - beg;
    int ocnt = __shfl_xor_sync(0xffffffffu, cnt, 16);
    int mx = cnt > ocnt ? cnt : ocnt;
    float4 den = make_float4(0.f,0.f,0.f,0.f);
    __half2 acc[4];
    acc[0]=acc[1]=acc[2]=acc[3]=__float2half2_rn(0.f);
    float2* myp = sp[wid][half];
    for (int b = 0; b < mx; b += 16){
        int j0 = b + sub;
        bool v = j0 < cnt;
        int cidx = v ? (beg + j0) : (end > beg ? end-1 : 0);
        int s = g_ssrc[cidx];
        float4 w = make_float4(0.f,0.f,0.f,0.f);
        if (v){
            float4 ae = sae[cidx];
            float4 as = asrc4[s];
            float ax = as.x+ad.x+ae.x; ax = ax>0.f?ax:0.2f*ax;
            float ay = as.y+ad.y+ae.y; ay = ay>0.f?ay:0.2f*ay;
            float az = as.z+ad.z+ae.z; az = az>0.f?az:0.2f*az;
            float aw = as.w+ad.w+ae.w; aw = aw>0.f?aw:0.2f*aw;
            w = make_float4(__expf(ax), __expf(ay), __expf(az), __expf(aw));
        }
        den.x += w.x; den.y += w.y; den.z += w.z; den.w += w.w;
        float so = __uint_as_float((unsigned)s * 256u);   // byte offset of fp16 row
        __syncwarp();
        myp[sub]      = make_float2(so, __uint_as_float(h2u(__float2half2_rn(w.x))));
        myp[17 + sub] = make_float2(so, __uint_as_float(h2u(__float2half2_rn(w.y))));
        myp[34 + sub] = make_float2(so, __uint_as_float(h2u(__float2half2_rn(w.z))));
        myp[51 + sub] = make_float2(so, __uint_as_float(h2u(__float2half2_rn(w.w))));
        __syncwarp();
        int jm = mx - b; if (jm > 16) jm = 16;
        const float2* hp2 = &myp[h*17];
        for (int c = 0; c < jm; c += 8){
            #pragma unroll
            for (int j = 0; j < 8; j++){
                float2 e2 = hp2[c+j];
                uint4 xr = *(const uint4*)(xbase + __float_as_uint(e2.x));
                unsigned wb = __float_as_uint(e2.y);
                __half2 wh = *reinterpret_cast<__half2*>(&wb);
                acc[0] = __hfma2(*reinterpret_cast<__half2*>(&xr.x), wh, acc[0]);
                acc[1] = __hfma2(*reinterpret_cast<__half2*>(&xr.y), wh, acc[1]);
                acc[2] = __hfma2(*reinterpret_cast<__half2*>(&xr.z), wh, acc[2]);
                acc[3] = __hfma2(*reinterpret_cast<__half2*>(&xr.w), wh, acc[3]);
            }
        }
    }
    // den reduce within half-warp (offsets < 16 keep halves separate)
    #pragma unroll
    for (int o=8;o>0;o>>=1){
        den.x += __shfl_xor_sync(0xffffffffu, den.x, o);
        den.y += __shfl_xor_sync(0xffffffffu, den.y, o);
        den.z += __shfl_xor_sync(0xffffffffu, den.z, o);
        den.w += __shfl_xor_sync(0xffffffffu, den.w, o);
    }
    float dh = (h==0)?den.x:(h==1)?den.y:(h==2)?den.z:den.w;
    float inv = 1.f/(dh + 1e-16f);
    const float* hp = conv ? g_h1 : g_h0;
    float*       ho = conv ? g_h2 : g_h1;
    float4 hva = nv ? *(const float4*)&hp[node*128 + sub*8]     : make_float4(0.f,0.f,0.f,0.f);
    float4 hvb = nv ? *(const float4*)&hp[node*128 + sub*8 + 4] : make_float4(0.f,0.f,0.f,0.f);
    float4 bva = *(const float4*)&bias[sub*8];
    float4 bvb = *(const float4*)&bias[sub*8+4];
    float2 f0 = __half22float2(acc[0]);
    float2 f1 = __half22float2(acc[1]);
    float2 f2 = __half22float2(acc[2]);
    float2 f3 = __half22float2(acc[3]);
    float fa[8] = {f0.x,f0.y,f1.x,f1.y,f2.x,f2.y,f3.x,f3.y};
    float hvv[8] = {hva.x,hva.y,hva.z,hva.w,hvb.x,hvb.y,hvb.z,hvb.w};
    float bvv[8] = {bva.x,bva.y,bva.z,bva.w,bvb.x,bvb.y,bvb.z,bvb.w};
    float ra[8];
    float s1 = 0.f, s2 = 0.f;
    #pragma unroll
    for (int i=0;i<8;i++){
        float r = fa[i]*inv + bvv[i];
        r = (r>0.f) ? r : (__expf(r)-1.f);
        r += hvv[i];
        ra[i] = r;
        s1 += r; s2 += r*r;
    }
    #pragma unroll
    for (int o=8;o>0;o>>=1){
        s1 += __shfl_xor_sync(0xffffffffu, s1, o);
        s2 += __shfl_xor_sync(0xffffffffu, s2, o);
    }
    float mu  = s1 * (1.f/128.f);
    float var = s2 * (1.f/128.f) - mu*mu;
    float rs  = rsqrtf(var + 1e-5f);
    float4 gva = *(const float4*)&gam[sub*8];
    float4 gvb = *(const float4*)&gam[sub*8+4];
    float4 bea = *(const float4*)&bet[sub*8];
    float4 beb = *(const float4*)&bet[sub*8+4];
    float gvv[8] = {gva.x,gva.y,gva.z,gva.w,gvb.x,gvb.y,gvb.z,gvb.w};
    float bev[8] = {bea.x,bea.y,bea.z,bea.w,beb.x,beb.y,beb.z,beb.w};
    float ov[8];
    #pragma unroll
    for (int i=0;i<8;i++) ov[i] = (ra[i]-mu)*rs*gvv[i] + bev[i];
    if (nv){
        float4 oa = make_float4(ov[0],ov[1],ov[2],ov[3]);
        float4 ob = make_float4(ov[4],ov[5],ov[6],ov[7]);
        *(float4*)&ho[node*128 + sub*8]     = oa;
        *(float4*)&ho[node*128 + sub*8 + 4] = ob;
    }
    if (conv){
        float4 a0a = nv ? *(const float4*)&g_h0[node*128 + sub*8]     : make_float4(0.f,0.f,0.f,0.f);
        float4 a0b = nv ? *(const float4*)&g_h0[node*128 + sub*8 + 4] : make_float4(0.f,0.f,0.f,0.f);
        float a0[8] = {a0a.x,a0a.y,a0a.z,a0a.w,a0b.x,a0b.y,a0b.z,a0b.w};
        float lg[5];
        #pragma unroll
        for (int c=0;c<5;c++){
            const float* w = &sCW[c*384];
            float4 b0a = *(const float4*)&w[sub*8];
            float4 b0b = *(const float4*)&w[sub*8+4];
            float4 b1a = *(const float4*)&w[128 + sub*8];
            float4 b1b = *(const float4*)&w[128 + sub*8+4];
            float4 b2a = *(const float4*)&w[256 + sub*8];
            float4 b2b = *(const float4*)&w[256 + sub*8+4];
            float w0[8] = {b0a.x,b0a.y,b0a.z,b0a.w,b0b.x,b0b.y,b0b.z,b0b.w};
            float w1[8] = {b1a.x,b1a.y,b1a.z,b1a.w,b1b.x,b1b.y,b1b.z,b1b.w};
            float w2[8] = {b2a.x,b2a.y,b2a.z,b2a.w,b2b.x,b2b.y,b2b.z,b2b.w};
            float p = 0.f;
            #pragma unroll
            for (int i=0;i<8;i++){
                p = fmaf(a0[i],  w0[i], p);
                p = fmaf(hvv[i], w1[i], p);
                p = fmaf(ov[i],  w2[i], p);
            }
            #pragma unroll
            for (int o=8;o>0;o>>=1) p += __shfl_xor_sync(0xffffffffu, p, o);
            lg[c] = p + sCB[c];
        }
        if (sub == 0 && nv){
            float m = lg[0];
            #pragma unroll
            for (int c=1;c<5;c++) m = fmaxf(m, lg[c]);
            float s = 0.f;
            #pragma unroll
            for (int c=0;c<5;c++) s += __expf(lg[c]-m);
            float ls = logf(s);
            #pragma unroll
            for (int c=0;c<5;c++) out[node*5+c] = lg[c]-m-ls;
        }
    }
}

// ---------------- conv2 GEMM + fused attention dots (fp16 xs output) ----------------
__global__ void __launch_bounds__(256) k_node2(const float* __restrict__ lin,
                                               const float* __restrict__ asv,
                                               const float* __restrict__ adv){
    __shared__ float sA[16*132];
    __shared__ float sB[16*132];
    int tid = threadIdx.x;
    int tx = tid & 15, ty = tid >> 4;
    int n0 = blockIdx.x*128;
    unsigned long long acc[8][4];
    #pragma unroll
    for (int r=0;r<8;r++)
        #pragma unroll
        for (int p=0;p<4;p++) acc[r][p] = 0ULL;
    for (int kc=0;kc<8;kc++){
        __syncthreads();
        #pragma unroll
        for (int t=tid;t<512;t+=256){
            int r = t>>2, q = t&3;
            int node = n0 + r;
            float4 v = (node<NN) ? *(const float4*)&g_h1[node*128 + kc*16 + q*4]
                                 : make_float4(0.f,0.f,0.f,0.f);
            sA[(q*4+0)*132+r]=v.x; sA[(q*4+1)*132+r]=v.y;
            sA[(q*4+2)*132+r]=v.z; sA[(q*4+3)*132+r]=v.w;
        }
        #pragma unroll
        for (int t=tid;t<512;t+=256){
            int d = t>>2, q = t&3;
            float4 v = *(const float4*)&lin[d*128 + kc*16 + q*4];
            sB[(q*4+0)*132+d]=v.x; sB[(q*4+1)*132+d]=v.y;
            sB[(q*4+2)*132+d]=v.z; sB[(q*4+3)*132+d]=v.w;
        }
        __syncthreads();
        #pragma unroll
        for (int k=0;k<16;k++){
            float4 a0 = *(const float4*)&sA[k*132 + ty*8];
            float4 a1 = *(const float4*)&sA[k*132 + ty*8 + 4];
            ulonglong2 b0 = *(const ulonglong2*)&sB[k*132 + tx*8];
            ulonglong2 b1 = *(const ulonglong2*)&sB[k*132 + tx*8 + 4];
            unsigned long long bp0=b0.x, bp1=b0.y, bp2=b1.x, bp3=b1.y;
            float ar[8] = {a0.x,a0.y,a0.z,a0.w,a1.x,a1.y,a1.z,a1.w};
            #pragma unroll
            for (int r=0;r<8;r++){
                unsigned long long a2 = pack2(ar[r]);
                fma2(acc[r][0], a2, bp0);
                fma2(acc[r][1], a2, bp1);
                fma2(acc[r][2], a2, bp2);
                fma2(acc[r][3], a2, bp3);
            }
        }
    }
    float4 ws0 = *(const float4*)&asv[tx*8];
    float4 ws1 = *(const float4*)&asv[tx*8+4];
    float4 wd0 = *(const float4*)&adv[tx*8];
    float4 wd1 = *(const float4*)&adv[tx*8+4];
    int hh = tx >> 2;
    #pragma unroll
    for (int r=0;r<8;r++){
        int node = n0 + ty*8 + r;
        if (node < NN){
            float f0=lo2(acc[r][0]), f1=hi2(acc[r][0]);
            float f2=lo2(acc[r][1]), f3=hi2(acc[r][1]);
            float f4=lo2(acc[r][2]), f5=hi2(acc[r][2]);
            float f6=lo2(acc[r][3]), f7=hi2(acc[r][3]);
            uint4 st;
            st.x = h2u(__floats2half2_rn(f0, f1));
            st.y = h2u(__floats2half2_rn(f2, f3));
            st.z = h2u(__floats2half2_rn(f4, f5));
            st.w = h2u(__floats2half2_rn(f6, f7));
            *(uint4*)(((char*)g_xsh) + node*256 + tx*16) = st;
            float s = f0*ws0.x + f1*ws0.y + f2*ws0.z + f3*ws0.w
                    + f4*ws1.x + f5*ws1.y + f6*ws1.z + f7*ws1.w;
            float d = f0*wd0.x + f1*wd0.y + f2*wd0.z + f3*wd0.w
                    + f4*wd1.x + f5*wd1.y + f6*wd1.z + f7*wd1.w;
            s += __shfl_xor_sync(0xffffffffu, s, 1);
            s += __shfl_xor_sync(0xffffffffu, s, 2);
            d += __shfl_xor_sync(0xffffffffu, d, 1);
            d += __shfl_xor_sync(0xffffffffu, d, 2);
            if ((tx & 3) == 0){
                g_asrc[node*4+hh] = s;
                g_adst[node*4+hh] = d;
            }
        }
    }
}

// ---------------- launcher ----------------
extern "C" void kernel_launch(void* const* d_in, const int* in_sizes, int n_in,
                              void* d_out, int out_size){
    const float* x      = (const float*)d_in[0];
    const int*   ei     = (const int*)  d_in[1];
    const float* ea     = (const float*)d_in[2];
    const float* ee_w1  = (const float*)d_in[3];
    const float* ee_b1  = (const float*)d_in[4];
    const float* ee_w2  = (const float*)d_in[5];
    const float* ee_b2  = (const float*)d_in[6];
    const float* proj_w = (const float*)d_in[7];
    const float* proj_b = (const float*)d_in[8];
    const float* c1_lin = (const float*)d_in[9];
    const float* c1_as  = (const float*)d_in[10];
    const float* c1_ad  = (const float*)d_in[11];
    const float* c1_le  = (const float*)d_in[12];
    const float* c1_ae  = (const float*)d_in[13];
    const float* c1_b   = (const float*)d_in[14];
    const float* c2_lin = (const float*)d_in[15];
    const float* c2_as  = (const float*)d_in[16];
    const float* c2_ad  = (const float*)d_in[17];
    const float* c2_le  = (const float*)d_in[18];
    const float* c2_ae  = (const float*)d_in[19];
    const float* c2_b   = (const float*)d_in[20];
    const float* n1_g   = (const float*)d_in[21];
    const float* n1_b   = (const float*)d_in[22];
    const float* n2_g   = (const float*)d_in[23];
    const float* n2_b   = (const float*)d_in[24];
    const float* jk_w   = (const float*)d_in[25];
    const float* jk_b   = (const float*)d_in[26];
    const float* cls_w  = (const float*)d_in[27];
    const float* cls_b  = (const float*)d_in[28];
    float* out = (float*)d_out;

    k_fused1<<<B_HIST+B_CW+1+B_NODE1,256>>>(ei, c1_le, c1_ae, c2_le, c2_ae,
                                            cls_w, cls_b, jk_w, jk_b,
                                            x, proj_w, proj_b, c1_lin, c1_as, c1_ad);
    k_scanab<<<98,512>>>();
    k_scanc<<<98,512>>>();
    k_edge<<<(QSTRIDE2+255)/256,256>>>(ea, ei, ee_w1, ee_b1, ee_w2, ee_b2);
    k_gat<<<(NN+31)/32,512>>>(c1_b, n1_g, n1_b, 0, out);
    k_node2<<<(NN+127)/128,256>>>(c2_lin, c2_as, c2_ad);
    k_gat<<<(NN+31)/32,512>>>(c2_b, n2_g, n2_b, 1, out);
}